// round 13
// baseline (speedup 1.0000x reference)
#include <cuda_runtime.h>
#include <cuda_bf16.h>
#include <cuda_fp16.h>
#include <math.h>
#include <stdint.h>

// Problem constants
#define NN   20000          // nodes
#define NE   320000         // edges
#define CC   128            // channels
#define KK   27             // kernel matrices
#define NBH  1792           // 28 blocks * 64 channels (half of output width)
#define EDGE_DIM 16
#define MLP_HID  6
#define SCAN_BLKS 79        // 79*256 >= NN

// ---------------- static device scratch ----------------
__device__ int   g_idx64;
__device__ int   g_src[NE];
__device__ int   g_dst[NE];
__device__ int   g_kbase[NE];
__device__ float g_bw[NE * 8];           // edge-ordered
// CSR by dst
__device__ int   g_cnt[NN];
__device__ int   g_rowptr[NN + 1];
__device__ int   g_woff[NN];
__device__ int   g_bsum[SCAN_BLKS];
__device__ int   g_bpre[SCAN_BLKS];
__device__ int   g_epack[NE];            // src | (kbase<<16), CSR order
__device__ float g_bwc[NE * 8];          // bw, CSR order
// GEMM buffers
__device__ __half g_XWh[(size_t)NN * NBH];            // 71.7 MB fp16 (one half at a time)
__device__ float  g_h[2][NN * CC];
// ping-pong bf16 activation hi/lo (avoid WAR between agg-split and 2nd-half GEMM)
__device__ __nv_bfloat16 g_xhi[2][NN * CC];
__device__ __nv_bfloat16 g_xlo[2][NN * CC];
// weights: [layer][half][row=k*64+o'][col=cin], rows 0..1791
__device__ __nv_bfloat16 g_bthi[3][2][(size_t)NBH * CC];
__device__ __nv_bfloat16 g_btlo[3][2][(size_t)NBH * CC];

// ---------------- index width detection ----------------
__global__ void detect_idx_kernel(const unsigned int* __restrict__ ei) {
    if (blockIdx.x == 0 && threadIdx.x == 0) {
        int is64 = 1;
        for (int i = 0; i < 4096; i++) {
            if (ei[2 * i + 1] != 0u) { is64 = 0; break; }
        }
        g_idx64 = is64;
    }
}

__global__ void zero_cnt_kernel() {
    int i = blockIdx.x * blockDim.x + threadIdx.x;
    if (i < NN) g_cnt[i] = 0;
}

// ---------------- edge preprocessing ----------------
__global__ void edge_pre_kernel(const void* __restrict__ ei_raw,
                                const float* __restrict__ ea,
                                const float* __restrict__ Wp1,
                                const float* __restrict__ bp1,
                                const float* __restrict__ Wp2,
                                const float* __restrict__ bp2) {
    int e = blockIdx.x * blockDim.x + threadIdx.x;
    if (e >= NE) return;

    int s, d;
    if (g_idx64) {
        const long long* p = (const long long*)ei_raw;
        s = (int)p[e];
        d = (int)p[NE + e];
    } else {
        const int* p = (const int*)ei_raw;
        s = p[e];
        d = p[NE + e];
    }
    g_src[e] = s;
    g_dst[e] = d;
    atomicAdd(&g_cnt[d], 1);

    float a[EDGE_DIM];
#pragma unroll
    for (int i = 0; i < EDGE_DIM; i++) a[i] = ea[(size_t)e * EDGE_DIM + i];

    float h[MLP_HID];
#pragma unroll
    for (int j = 0; j < MLP_HID; j++) {
        float z = bp1[j];
#pragma unroll
        for (int i = 0; i < EDGE_DIM; i++) z += a[i] * Wp1[i * MLP_HID + j];
        h[j] = fmaxf(z, 0.0f);
    }

    float fr[3];
    int lo[3];
#pragma unroll
    for (int dd = 0; dd < 3; dd++) {
        float z = bp2[dd];
#pragma unroll
        for (int j = 0; j < MLP_HID; j++) z += h[j] * Wp2[j * 3 + dd];
        float u = 1.0f / (1.0f + expf(-z));
        float v = u * 2.0f;
        float l = fminf(fmaxf(floorf(v), 0.0f), 1.0f);
        lo[dd] = (int)l;
        fr[dd] = v - l;
    }
    g_kbase[e] = lo[0] + 3 * lo[1] + 9 * lo[2];

#pragma unroll
    for (int sb = 0; sb < 8; sb++) {
        float w = ((sb & 1) ? fr[0] : 1.0f - fr[0])
                * ((sb & 2) ? fr[1] : 1.0f - fr[1])
                * ((sb & 4) ? fr[2] : 1.0f - fr[2]);
        g_bw[(size_t)e * 8 + sb] = w;
    }
}

// ---------------- 3-phase scan ----------------
__global__ void blocksum_kernel() {
    __shared__ int sh[256];
    int idx = blockIdx.x * 256 + threadIdx.x;
    int c = (idx < NN) ? g_cnt[idx] : 0;
    sh[threadIdx.x] = c;
    __syncthreads();
    for (int s = 128; s > 0; s >>= 1) {
        if (threadIdx.x < s) sh[threadIdx.x] += sh[threadIdx.x + s];
        __syncthreads();
    }
    if (threadIdx.x == 0) g_bsum[blockIdx.x] = sh[0];
}

__global__ void scanpart_kernel() {
    __shared__ int sh[128];
    int t = threadIdx.x;
    int v = (t < SCAN_BLKS) ? g_bsum[t] : 0;
    sh[t] = v;
    __syncthreads();
    for (int d = 1; d < 128; d <<= 1) {
        int u = (t >= d) ? sh[t - d] : 0;
        __syncthreads();
        sh[t] += u;
        __syncthreads();
    }
    if (t < SCAN_BLKS) g_bpre[t] = sh[t] - v;
    if (t == 0) g_rowptr[NN] = NE;
}

__global__ void rowptr_kernel() {
    __shared__ int sh[256];
    int idx = blockIdx.x * 256 + threadIdx.x;
    int t = threadIdx.x;
    int c = (idx < NN) ? g_cnt[idx] : 0;
    sh[t] = c;
    __syncthreads();
    for (int d = 1; d < 256; d <<= 1) {
        int u = (t >= d) ? sh[t - d] : 0;
        __syncthreads();
        sh[t] += u;
        __syncthreads();
    }
    if (idx < NN) {
        int excl = g_bpre[blockIdx.x] + sh[t] - c;
        g_rowptr[idx] = excl;
        g_woff[idx] = excl;
    }
}

__global__ void scatter_kernel() {
    int e = blockIdx.x * blockDim.x + threadIdx.x;
    if (e >= NE) return;
    int d = g_dst[e];
    int pos = atomicAdd(&g_woff[d], 1);
    g_epack[pos] = g_src[e] | (g_kbase[e] << 16);
#pragma unroll
    for (int t = 0; t < 8; t++) g_bwc[(size_t)pos * 8 + t] = g_bw[(size_t)e * 8 + t];
}

// -------- W [K,Cin,H] fp32 -> half-split Bt: [half][k*64+o'][cin], bf16 hi/lo --------
__global__ void conv_w_kernel(const float* __restrict__ W,
                              __nv_bfloat16* __restrict__ hi,
                              __nv_bfloat16* __restrict__ lo) {
    int idx = blockIdx.x * blockDim.x + threadIdx.x;
    if (idx >= KK * CC * CC) return;
    int o = idx & 127;
    int i = (idx >> 7) & 127;
    int k = idx >> 14;
    float v = W[idx];
    __nv_bfloat16 h = __float2bfloat16(v);
    size_t n = (size_t)(o >> 6) * NBH * CC + (size_t)(k * 64 + (o & 63)) * CC + i;
    hi[n] = h;
    lo[n] = __float2bfloat16(v - __bfloat162float(h));
}

// -------- Wr [Cin,H] appended as block 27 --------
__global__ void conv_wr_kernel(const float* __restrict__ Wr,
                               __nv_bfloat16* __restrict__ hi,
                               __nv_bfloat16* __restrict__ lo) {
    int idx = blockIdx.x * blockDim.x + threadIdx.x;
    if (idx >= CC * CC) return;
    int o = idx & 127;
    int i = idx >> 7;
    float v = Wr[idx];
    __nv_bfloat16 h = __float2bfloat16(v);
    size_t n = (size_t)(o >> 6) * NBH * CC + (size_t)(27 * 64 + (o & 63)) * CC + i;
    hi[n] = h;
    lo[n] = __float2bfloat16(v - __bfloat162float(h));
}

// -------- activation fp32 -> bf16 hi/lo split (layer 0 only) --------
__global__ void convert_act_kernel(const float* __restrict__ a,
                                   __nv_bfloat16* __restrict__ hi,
                                   __nv_bfloat16* __restrict__ lo) {
    int i = blockIdx.x * blockDim.x + threadIdx.x;
    if (i >= NN * CC) return;
    float v = a[i];
    __nv_bfloat16 h = __float2bfloat16(v);
    hi[i] = h;
    lo[i] = __float2bfloat16(v - __bfloat162float(h));
}

// ================= HMMA (mma.sync bf16) split GEMM: XWh = act @ Bt^T =================
#define SM_AHI 0
#define SM_BHI 32768
#define SM_X   65536
#define SMEM_TOT 98304

__device__ __forceinline__ uint32_t smem_u32(const void* p) {
    uint32_t a;
    asm("{ .reg .u64 t; cvta.to.shared.u64 t, %1; cvt.u32.u64 %0, t; }" : "=r"(a) : "l"(p));
    return a;
}
__device__ __forceinline__ uint32_t sw_off(int row, int kc) {
    return (uint32_t)(row * 256 + ((kc ^ (row & 7)) << 4));
}
__device__ __forceinline__ void load_tile(char* smem, int off,
                                          const __nv_bfloat16* __restrict__ src,
                                          int row_base, int row_max, int tid) {
#pragma unroll
    for (int it = 0; it < 8; it++) {
        int idx = it * 256 + tid;
        int row = idx >> 4, kc = idx & 15;
        int grow = row_base + row;
        uint4 v = make_uint4(0u, 0u, 0u, 0u);
        if (grow < row_max)
            v = *(const uint4*)(src + (size_t)grow * CC + kc * 8);
        *(uint4*)(smem + off + sw_off(row, kc)) = v;
    }
}
__device__ __forceinline__ void ldmatrix_x4(uint32_t* r, uint32_t addr) {
    asm volatile("ldmatrix.sync.aligned.m8n8.x4.shared.b16 {%0,%1,%2,%3}, [%4];"
                 : "=r"(r[0]), "=r"(r[1]), "=r"(r[2]), "=r"(r[3]) : "r"(addr));
}
__device__ __forceinline__ void mma16816(float* c, const uint32_t* a, const uint32_t* b) {
    asm volatile(
        "mma.sync.aligned.m16n8k16.row.col.f32.bf16.bf16.f32 "
        "{%0,%1,%2,%3}, {%4,%5,%6,%7}, {%8,%9}, {%0,%1,%2,%3};"
        : "+f"(c[0]), "+f"(c[1]), "+f"(c[2]), "+f"(c[3])
        : "r"(a[0]), "r"(a[1]), "r"(a[2]), "r"(a[3]), "r"(b[0]), "r"(b[1]));
}

__global__ void __launch_bounds__(256, 2)
xw_hmma_kernel(const __nv_bfloat16* __restrict__ xhi,
               const __nv_bfloat16* __restrict__ xlo,
               const __nv_bfloat16* __restrict__ bthi,
               const __nv_bfloat16* __restrict__ btlo,
               __half* __restrict__ XWh) {
    extern __shared__ __align__(1024) char smem[];
    const int tid  = threadIdx.x;
    const int wid  = tid >> 5;
    const int lane = tid & 31;
    const int bn = blockIdx.x * 128;
    const int bm = blockIdx.y * 128;

    load_tile(smem, SM_AHI, xhi,  bm, NN, tid);
    load_tile(smem, SM_BHI, bthi, bn, NBH, tid);
    load_tile(smem, SM_X,   xlo,  bm, NN, tid);
    __syncthreads();

    const uint32_t sbase = smem_u32(smem);
    const int m_base = (wid & 1) * 64;
    const int n_base = (wid >> 1) * 32;

    float acc[4][4][4];
#pragma unroll
    for (int mt = 0; mt < 4; mt++)
#pragma unroll
        for (int nt = 0; nt < 4; nt++)
#pragma unroll
            for (int q = 0; q < 4; q++) acc[mt][nt][q] = 0.0f;

    const int a_row_in = (lane & 15);
    const int a_kadd   = (lane >> 4);
    const int b_row_in = ((lane >> 4) << 3) + (lane & 7);
    const int b_kadd   = ((lane >> 3) & 1);

    auto run_pass = [&](int offA, int offB) {
        const uint32_t abase = sbase + offA;
        const uint32_t bbase = sbase + offB;
#pragma unroll
        for (int ks = 0; ks < 8; ks++) {
            const int kc = ks * 2;
            uint32_t afrag[4][4];
#pragma unroll
            for (int mt = 0; mt < 4; mt++) {
                int row = m_base + mt * 16 + a_row_in;
                ldmatrix_x4(afrag[mt], abase + sw_off(row, kc + a_kadd));
            }
            uint32_t bfrag[4][2];
#pragma unroll
            for (int g = 0; g < 2; g++) {
                uint32_t r[4];
                int nrow = n_base + g * 16 + b_row_in;
                ldmatrix_x4(r, bbase + sw_off(nrow, kc + b_kadd));
                bfrag[2 * g][0]     = r[0];
                bfrag[2 * g][1]     = r[1];
                bfrag[2 * g + 1][0] = r[2];
                bfrag[2 * g + 1][1] = r[3];
            }
#pragma unroll
            for (int mt = 0; mt < 4; mt++)
#pragma unroll
                for (int nt = 0; nt < 4; nt++)
                    mma16816(acc[mt][nt], afrag[mt], bfrag[nt]);
        }
    };

    run_pass(SM_AHI, SM_BHI);   // Ahi * Bhi
    run_pass(SM_X,   SM_BHI);   // Alo * Bhi
    __syncthreads();
    load_tile(smem, SM_X, btlo, bn, NBH, tid);   // X := Blo
    __syncthreads();
    run_pass(SM_AHI, SM_X);     // Ahi * Blo

    // epilogue: fp16 store
    const int qrow = lane >> 2;
    const int qcol = (lane & 3) * 2;
#pragma unroll
    for (int mt = 0; mt < 4; mt++) {
        int r0 = bm + m_base + mt * 16 + qrow;
        int r1 = r0 + 8;
#pragma unroll
        for (int nt = 0; nt < 4; nt++) {
            int col = bn + n_base + nt * 8 + qcol;
            if (r0 < NN) {
                __half2 h = __floats2half2_rn(acc[mt][nt][0], acc[mt][nt][1]);
                *(uint32_t*)(XWh + (size_t)r0 * NBH + col) = *(uint32_t*)&h;
            }
            if (r1 < NN) {
                __half2 h = __floats2half2_rn(acc[mt][nt][2], acc[mt][nt][3]);
                *(uint32_t*)(XWh + (size_t)r1 * NBH + col) = *(uint32_t*)&h;
            }
        }
    }
}

// ======== fused aggregation (one channel-half): 64 ch, 2 per lane ========
__global__ void __launch_bounds__(256)
agg_csr_kernel(const __half* __restrict__ XWh,
               const float* __restrict__ bias,
               float* __restrict__ out,
               __nv_bfloat16* __restrict__ hi,
               __nv_bfloat16* __restrict__ lo,
               int half, int doRelu, int doSplit) {
    const int n = blockIdx.x * 8 + (threadIdx.x >> 5);
    const int lane = threadIdx.x & 31;
    if (n >= NN) return;
    const int OFF[8] = {0, 64, 192, 256, 576, 640, 768, 832};  // {0,1,3,4,9,10,12,13}*64

    // bias + root block (tap 27 of own node)
    float2 bb = *(const float2*)(bias + half * 64 + lane * 2);
    float a0 = bb.x, a1 = bb.y;
    {
        uint32_t v = *(const uint32_t*)(XWh + (size_t)n * NBH + 27 * 64 + lane * 2);
        float2 f = __half22float2(*(__half2*)&v);
        a0 += f.x; a1 += f.y;
    }

    const int beg = g_rowptr[n];
    const int end = g_rowptr[n + 1];
    for (int i = beg; i < end; i++) {
        int packed = g_epack[i];
        int src = packed & 0xffff;
        int kb  = packed >> 16;
        float wv = (lane < 8) ? g_bwc[(size_t)i * 8 + lane] : 0.0f;
        const __half* base = XWh + (size_t)src * NBH + (size_t)kb * 64 + lane * 2;
#pragma unroll
        for (int t = 0; t < 8; t++) {
            float w = __shfl_sync(0xffffffffu, wv, t);
            uint32_t v = *(const uint32_t*)(base + OFF[t]);
            float2 f = __half22float2(*(__half2*)&v);
            a0 += w * f.x; a1 += w * f.y;
        }
    }

    if (doRelu) {
        a0 = fmaxf(a0, 0.f); a1 = fmaxf(a1, 0.f);
    }
    const int co = half * 64 + lane * 2;
    *(float2*)(out + (size_t)n * CC + co) = make_float2(a0, a1);

    if (doSplit) {
        __nv_bfloat16 h0 = __float2bfloat16(a0);
        __nv_bfloat16 h1 = __float2bfloat16(a1);
        __nv_bfloat16 l0 = __float2bfloat16(a0 - __bfloat162float(h0));
        __nv_bfloat16 l1 = __float2bfloat16(a1 - __bfloat162float(h1));
        __nv_bfloat16 hh[2] = {h0, h1};
        __nv_bfloat16 ll[2] = {l0, l1};
        *(uint32_t*)(hi + (size_t)n * CC + co) = *(uint32_t*)hh;
        *(uint32_t*)(lo + (size_t)n * CC + co) = *(uint32_t*)ll;
    }
}

// ---------------- launch ----------------
extern "C" void kernel_launch(void* const* d_in, const int* in_sizes, int n_in,
                              void* d_out, int out_size) {
    const float* x    = (const float*)d_in[0];
    const void*  ei   = d_in[1];
    const float* ea   = (const float*)d_in[2];
    const float* Wp1  = (const float*)d_in[3];
    const float* bp1  = (const float*)d_in[4];
    const float* Wp2  = (const float*)d_in[5];
    const float* bp2  = (const float*)d_in[6];
    const float* W[3]  = {(const float*)d_in[7],  (const float*)d_in[10], (const float*)d_in[13]};
    const float* Wr[3] = {(const float*)d_in[8],  (const float*)d_in[11], (const float*)d_in[14]};
    const float* b[3]  = {(const float*)d_in[9],  (const float*)d_in[12], (const float*)d_in[15]};
    float* out_final = (float*)d_out;

    float* g_h_p;    cudaGetSymbolAddress((void**)&g_h_p, g_h);
    __half* xwh_p;   cudaGetSymbolAddress((void**)&xwh_p, g_XWh);
    __nv_bfloat16* xhi_p;  cudaGetSymbolAddress((void**)&xhi_p, g_xhi);
    __nv_bfloat16* xlo_p;  cudaGetSymbolAddress((void**)&xlo_p, g_xlo);
    __nv_bfloat16* bthi_p; cudaGetSymbolAddress((void**)&bthi_p, g_bthi);
    __nv_bfloat16* btlo_p; cudaGetSymbolAddress((void**)&btlo_p, g_btlo);

    cudaFuncSetAttribute(xw_hmma_kernel, cudaFuncAttributeMaxDynamicSharedMemorySize, SMEM_TOT);

    // 1) edge preprocessing + CSR build
    detect_idx_kernel<<<1, 32>>>((const unsigned int*)ei);
    zero_cnt_kernel<<<(NN + 255) / 256, 256>>>();
    edge_pre_kernel<<<(NE + 255) / 256, 256>>>(ei, ea, Wp1, bp1, Wp2, bp2);
    blocksum_kernel<<<SCAN_BLKS, 256>>>();
    scanpart_kernel<<<1, 128>>>();
    rowptr_kernel<<<SCAN_BLKS, 256>>>();
    scatter_kernel<<<(NE + 255) / 256, 256>>>();

    // 2) weights: transpose + bf16-split + half-split, root appended as block 27
    const size_t LSTRIDE = (size_t)2 * NBH * CC;   // per-layer (2 halves)
    for (int l = 0; l < 3; l++) {
        conv_w_kernel<<<(KK * CC * CC + 255) / 256, 256>>>(
            W[l], bthi_p + l * LSTRIDE, btlo_p + l * LSTRIDE);
        conv_wr_kernel<<<(CC * CC + 255) / 256, 256>>>(
            Wr[l], bthi_p + l * LSTRIDE, btlo_p + l * LSTRIDE);
    }

    // 3) layer-0 activation split into ping-pong slot 0
    convert_act_kernel<<<(NN * CC + 255) / 256, 256>>>(x, xhi_p, xlo_p);

    // 4) three layers, two channel-halves each (GEMM -> agg per half, L2-resident).
    //    Activations ping-pong: layer l reads slot l&1, agg-split writes slot (l+1)&1,
    //    so the half-1 GEMM's input is never overwritten by the half-0 agg.
    dim3 gridXW(NBH / 128, (NN + 127) / 128);   // 14 x 157
    int aggBlocks = (NN + 7) / 8;
    const size_t XS = (size_t)NN * CC;          // ping-pong slot stride

    for (int l = 0; l < 3; l++) {
        float* outbuf = (l == 2) ? out_final : (g_h_p + (size_t)l * NN * CC);
        const int cur = l & 1, nxt = (l + 1) & 1;
        for (int half = 0; half < 2; half++) {
            xw_hmma_kernel<<<gridXW, 256, SMEM_TOT>>>(
                xhi_p + cur * XS, xlo_p + cur * XS,
                bthi_p + l * LSTRIDE + (size_t)half * NBH * CC,
                btlo_p + l * LSTRIDE + (size_t)half * NBH * CC,
                xwh_p);

            agg_csr_kernel<<<aggBlocks, 256>>>(
                xwh_p, b[l], outbuf, xhi_p + nxt * XS, xlo_p + nxt * XS,
                half, /*doRelu=*/(l < 2) ? 1 : 0, /*doSplit=*/(l < 2) ? 1 : 0);
        }
    }
}

// round 14
// speedup vs baseline: 1.2170x; 1.2170x over previous
#include <cuda_runtime.h>
#include <cuda_fp16.h>
#include <math.h>
#include <stdint.h>

// Problem constants
#define NN   20000          // nodes
#define NE   320000         // edges
#define CC   128            // channels
#define KK   27             // kernel matrices
#define NB2  (28 * CC)      // 3584 = 27 kernel blocks + 1 root block
#define EDGE_DIM 16
#define MLP_HID  6
#define SCAN_BLKS 79        // 79*256 >= NN

// ---------------- static device scratch ----------------
__device__ int   g_idx64;
__device__ int   g_src[NE];
__device__ int   g_dst[NE];
__device__ int   g_kbase[NE];
__device__ float g_bw[NE * 8];           // edge-ordered
// CSR by dst
__device__ int   g_cnt[NN];
__device__ int   g_rowptr[NN + 1];
__device__ int   g_woff[NN];
__device__ int   g_bsum[SCAN_BLKS];
__device__ int   g_bpre[SCAN_BLKS];
__device__ int   g_epack[NE];            // src | (kbase<<16), CSR order
__device__ float g_bwc[NE * 8];          // bw, CSR order
// GEMM buffers
__device__ __half g_XWh[(size_t)NN * NB2];            // 143 MB fp16
__device__ float  g_h[NN * CC];                       // fp32 out (layer 2 handled via d_out)
__device__ __half g_xhi[NN * CC];                     // activation hi (fp16)
__device__ __half g_xlo[NN * CC];                     // activation lo residual (fp16)
__device__ __half g_bt[3][(size_t)NB2 * CC];          // W^T fp16: [row=k*128+o][col=cin]

// ---------------- index width detection ----------------
__global__ void detect_idx_kernel(const unsigned int* __restrict__ ei) {
    if (blockIdx.x == 0 && threadIdx.x == 0) {
        int is64 = 1;
        for (int i = 0; i < 4096; i++) {
            if (ei[2 * i + 1] != 0u) { is64 = 0; break; }
        }
        g_idx64 = is64;
    }
}

__global__ void zero_cnt_kernel() {
    int i = blockIdx.x * blockDim.x + threadIdx.x;
    if (i < NN) g_cnt[i] = 0;
}

// ---------------- edge preprocessing ----------------
__global__ void edge_pre_kernel(const void* __restrict__ ei_raw,
                                const float* __restrict__ ea,
                                const float* __restrict__ Wp1,
                                const float* __restrict__ bp1,
                                const float* __restrict__ Wp2,
                                const float* __restrict__ bp2) {
    int e = blockIdx.x * blockDim.x + threadIdx.x;
    if (e >= NE) return;

    int s, d;
    if (g_idx64) {
        const long long* p = (const long long*)ei_raw;
        s = (int)p[e];
        d = (int)p[NE + e];
    } else {
        const int* p = (const int*)ei_raw;
        s = p[e];
        d = p[NE + e];
    }
    g_src[e] = s;
    g_dst[e] = d;
    atomicAdd(&g_cnt[d], 1);

    float a[EDGE_DIM];
#pragma unroll
    for (int i = 0; i < EDGE_DIM; i++) a[i] = ea[(size_t)e * EDGE_DIM + i];

    float h[MLP_HID];
#pragma unroll
    for (int j = 0; j < MLP_HID; j++) {
        float z = bp1[j];
#pragma unroll
        for (int i = 0; i < EDGE_DIM; i++) z += a[i] * Wp1[i * MLP_HID + j];
        h[j] = fmaxf(z, 0.0f);
    }

    float fr[3];
    int lo[3];
#pragma unroll
    for (int dd = 0; dd < 3; dd++) {
        float z = bp2[dd];
#pragma unroll
        for (int j = 0; j < MLP_HID; j++) z += h[j] * Wp2[j * 3 + dd];
        float u = 1.0f / (1.0f + expf(-z));
        float v = u * 2.0f;
        float l = fminf(fmaxf(floorf(v), 0.0f), 1.0f);
        lo[dd] = (int)l;
        fr[dd] = v - l;
    }
    g_kbase[e] = lo[0] + 3 * lo[1] + 9 * lo[2];

#pragma unroll
    for (int sb = 0; sb < 8; sb++) {
        float w = ((sb & 1) ? fr[0] : 1.0f - fr[0])
                * ((sb & 2) ? fr[1] : 1.0f - fr[1])
                * ((sb & 4) ? fr[2] : 1.0f - fr[2]);
        g_bw[(size_t)e * 8 + sb] = w;
    }
}

// ---------------- 3-phase scan ----------------
__global__ void blocksum_kernel() {
    __shared__ int sh[256];
    int idx = blockIdx.x * 256 + threadIdx.x;
    int c = (idx < NN) ? g_cnt[idx] : 0;
    sh[threadIdx.x] = c;
    __syncthreads();
    for (int s = 128; s > 0; s >>= 1) {
        if (threadIdx.x < s) sh[threadIdx.x] += sh[threadIdx.x + s];
        __syncthreads();
    }
    if (threadIdx.x == 0) g_bsum[blockIdx.x] = sh[0];
}

__global__ void scanpart_kernel() {
    __shared__ int sh[128];
    int t = threadIdx.x;
    int v = (t < SCAN_BLKS) ? g_bsum[t] : 0;
    sh[t] = v;
    __syncthreads();
    for (int d = 1; d < 128; d <<= 1) {
        int u = (t >= d) ? sh[t - d] : 0;
        __syncthreads();
        sh[t] += u;
        __syncthreads();
    }
    if (t < SCAN_BLKS) g_bpre[t] = sh[t] - v;
    if (t == 0) g_rowptr[NN] = NE;
}

__global__ void rowptr_kernel() {
    __shared__ int sh[256];
    int idx = blockIdx.x * 256 + threadIdx.x;
    int t = threadIdx.x;
    int c = (idx < NN) ? g_cnt[idx] : 0;
    sh[t] = c;
    __syncthreads();
    for (int d = 1; d < 256; d <<= 1) {
        int u = (t >= d) ? sh[t - d] : 0;
        __syncthreads();
        sh[t] += u;
        __syncthreads();
    }
    if (idx < NN) {
        int excl = g_bpre[blockIdx.x] + sh[t] - c;
        g_rowptr[idx] = excl;
        g_woff[idx] = excl;
    }
}

__global__ void scatter_kernel() {
    int e = blockIdx.x * blockDim.x + threadIdx.x;
    if (e >= NE) return;
    int d = g_dst[e];
    int pos = atomicAdd(&g_woff[d], 1);
    g_epack[pos] = g_src[e] | (g_kbase[e] << 16);
#pragma unroll
    for (int t = 0; t < 8; t++) g_bwc[(size_t)pos * 8 + t] = g_bw[(size_t)e * 8 + t];
}

// -------- W [K,Cin,H] fp32 -> Bt [(k*H+o), Cin] fp16 --------
__global__ void conv_w_kernel(const float* __restrict__ W, __half* __restrict__ bt) {
    int idx = blockIdx.x * blockDim.x + threadIdx.x;
    if (idx >= KK * CC * CC) return;
    int o = idx & 127;
    int i = (idx >> 7) & 127;
    int k = idx >> 14;
    bt[(size_t)(k * CC + o) * CC + i] = __float2half_rn(W[idx]);
}

// -------- Wr [Cin,H] appended as block 27 --------
__global__ void conv_wr_kernel(const float* __restrict__ Wr, __half* __restrict__ bt) {
    int idx = blockIdx.x * blockDim.x + threadIdx.x;
    if (idx >= CC * CC) return;
    int o = idx & 127;
    int i = idx >> 7;
    bt[(size_t)(27 * CC + o) * CC + i] = __float2half_rn(Wr[idx]);
}

// -------- activation fp32 -> fp16 hi/lo split (layer 0 only) --------
__global__ void convert_act_kernel(const float* __restrict__ a,
                                   __half* __restrict__ hi,
                                   __half* __restrict__ lo) {
    int i = blockIdx.x * blockDim.x + threadIdx.x;
    if (i >= NN * CC) return;
    float v = a[i];
    __half h = __float2half_rn(v);
    hi[i] = h;
    lo[i] = __float2half_rn(v - __half2float(h));
}

// ================= HMMA (mma.sync fp16) 2-pass GEMM: XWh = act @ Bt^T =================
// D = Ahi*B + Alo*B, fp32 accum. SMEM: Ahi | Alo | B, each 32KB, XOR-swizzled.
#define SM_AHI 0
#define SM_ALO 32768
#define SM_B   65536
#define SMEM_TOT 98304

__device__ __forceinline__ uint32_t smem_u32(const void* p) {
    uint32_t a;
    asm("{ .reg .u64 t; cvta.to.shared.u64 t, %1; cvt.u32.u64 %0, t; }" : "=r"(a) : "l"(p));
    return a;
}
__device__ __forceinline__ uint32_t sw_off(int row, int kc) {
    return (uint32_t)(row * 256 + ((kc ^ (row & 7)) << 4));
}
__device__ __forceinline__ void load_tile(char* smem, int off,
                                          const __half* __restrict__ src,
                                          int row_base, int row_max, int tid) {
#pragma unroll
    for (int it = 0; it < 8; it++) {
        int idx = it * 256 + tid;
        int row = idx >> 4, kc = idx & 15;
        int grow = row_base + row;
        uint4 v = make_uint4(0u, 0u, 0u, 0u);
        if (grow < row_max)
            v = *(const uint4*)(src + (size_t)grow * CC + kc * 8);
        *(uint4*)(smem + off + sw_off(row, kc)) = v;
    }
}
__device__ __forceinline__ void ldmatrix_x4(uint32_t* r, uint32_t addr) {
    asm volatile("ldmatrix.sync.aligned.m8n8.x4.shared.b16 {%0,%1,%2,%3}, [%4];"
                 : "=r"(r[0]), "=r"(r[1]), "=r"(r[2]), "=r"(r[3]) : "r"(addr));
}
__device__ __forceinline__ void mma16816(float* c, const uint32_t* a, const uint32_t* b) {
    asm volatile(
        "mma.sync.aligned.m16n8k16.row.col.f32.f16.f16.f32 "
        "{%0,%1,%2,%3}, {%4,%5,%6,%7}, {%8,%9}, {%0,%1,%2,%3};"
        : "+f"(c[0]), "+f"(c[1]), "+f"(c[2]), "+f"(c[3])
        : "r"(a[0]), "r"(a[1]), "r"(a[2]), "r"(a[3]), "r"(b[0]), "r"(b[1]));
}

__global__ void __launch_bounds__(256, 2)
xw_hmma_kernel(const __half* __restrict__ xhi,
               const __half* __restrict__ xlo,
               const __half* __restrict__ bt,
               __half* __restrict__ XWh) {
    extern __shared__ __align__(1024) char smem[];
    const int tid  = threadIdx.x;
    const int wid  = tid >> 5;
    const int lane = tid & 31;
    const int bn = blockIdx.x * 128;
    const int bm = blockIdx.y * 128;

    load_tile(smem, SM_AHI, xhi, bm, NN, tid);
    load_tile(smem, SM_B,   bt,  bn, NB2, tid);
    load_tile(smem, SM_ALO, xlo, bm, NN, tid);
    __syncthreads();

    const uint32_t sbase = smem_u32(smem);
    const int m_base = (wid & 1) * 64;
    const int n_base = (wid >> 1) * 32;

    float acc[4][4][4];
#pragma unroll
    for (int mt = 0; mt < 4; mt++)
#pragma unroll
        for (int nt = 0; nt < 4; nt++)
#pragma unroll
            for (int q = 0; q < 4; q++) acc[mt][nt][q] = 0.0f;

    const int a_row_in = (lane & 15);
    const int a_kadd   = (lane >> 4);
    const int b_row_in = ((lane >> 4) << 3) + (lane & 7);
    const int b_kadd   = ((lane >> 3) & 1);

    auto run_pass = [&](int offA) {
        const uint32_t abase = sbase + offA;
        const uint32_t bbase = sbase + SM_B;
#pragma unroll
        for (int ks = 0; ks < 8; ks++) {
            const int kc = ks * 2;
            uint32_t afrag[4][4];
#pragma unroll
            for (int mt = 0; mt < 4; mt++) {
                int row = m_base + mt * 16 + a_row_in;
                ldmatrix_x4(afrag[mt], abase + sw_off(row, kc + a_kadd));
            }
            uint32_t bfrag[4][2];
#pragma unroll
            for (int g = 0; g < 2; g++) {
                uint32_t r[4];
                int nrow = n_base + g * 16 + b_row_in;
                ldmatrix_x4(r, bbase + sw_off(nrow, kc + b_kadd));
                bfrag[2 * g][0]     = r[0];
                bfrag[2 * g][1]     = r[1];
                bfrag[2 * g + 1][0] = r[2];
                bfrag[2 * g + 1][1] = r[3];
            }
#pragma unroll
            for (int mt = 0; mt < 4; mt++)
#pragma unroll
                for (int nt = 0; nt < 4; nt++)
                    mma16816(acc[mt][nt], afrag[mt], bfrag[nt]);
        }
    };

    run_pass(SM_AHI);   // Ahi * B
    run_pass(SM_ALO);   // Alo * B

    // epilogue: fp16 store
    const int qrow = lane >> 2;
    const int qcol = (lane & 3) * 2;
#pragma unroll
    for (int mt = 0; mt < 4; mt++) {
        int r0 = bm + m_base + mt * 16 + qrow;
        int r1 = r0 + 8;
#pragma unroll
        for (int nt = 0; nt < 4; nt++) {
            int col = bn + n_base + nt * 8 + qcol;
            if (r0 < NN) {
                __half2 h = __floats2half2_rn(acc[mt][nt][0], acc[mt][nt][1]);
                *(uint32_t*)(XWh + (size_t)r0 * NB2 + col) = *(uint32_t*)&h;
            }
            if (r1 < NN) {
                __half2 h = __floats2half2_rn(acc[mt][nt][2], acc[mt][nt][3]);
                *(uint32_t*)(XWh + (size_t)r1 * NB2 + col) = *(uint32_t*)&h;
            }
        }
    }
}

// ======== fused aggregation: bias + root + edges, 2-edge software pipeline ========
__global__ void __launch_bounds__(256)
agg_csr_kernel(const __half* __restrict__ XWh,
               const float* __restrict__ bias,
               float* __restrict__ out,
               __half* __restrict__ hi,
               __half* __restrict__ lo,
               int doRelu, int doOut, int doSplit) {
    const int n = blockIdx.x * 8 + (threadIdx.x >> 5);
    const int lane = threadIdx.x & 31;
    if (n >= NN) return;
    const int OFF[8] = {0, 128, 384, 512, 1152, 1280, 1536, 1664};  // {0,1,3,4,9,10,12,13}*CC

    float4 bb = *(const float4*)(bias + lane * 4);
    float a0 = bb.x, a1 = bb.y, a2 = bb.z, a3 = bb.w;
    {
        uint2 v = *(const uint2*)(XWh + (size_t)n * NB2 + 27 * CC + lane * 4);
        float2 f0 = __half22float2(*(__half2*)&v.x);
        float2 f1 = __half22float2(*(__half2*)&v.y);
        a0 += f0.x; a1 += f0.y; a2 += f1.x; a3 += f1.y;
    }

    const int beg = g_rowptr[n];
    const int end = g_rowptr[n + 1];
    int i = beg;
    // 2-edge pipelined main loop: one 64B bw read serves both edges (lanes 0-15)
    for (; i + 2 <= end; i += 2) {
        int p0 = g_epack[i];
        int p1 = g_epack[i + 1];
        float wv = (lane < 16) ? g_bwc[(size_t)i * 8 + lane] : 0.0f;
        const __half* base0 = XWh + (size_t)(p0 & 0xffff) * NB2 + (size_t)(p0 >> 16) * CC + lane * 4;
        const __half* base1 = XWh + (size_t)(p1 & 0xffff) * NB2 + (size_t)(p1 >> 16) * CC + lane * 4;
#pragma unroll
        for (int t = 0; t < 8; t++) {
            float w0 = __shfl_sync(0xffffffffu, wv, t);
            float w1 = __shfl_sync(0xffffffffu, wv, t + 8);
            uint2 v0 = *(const uint2*)(base0 + OFF[t]);
            uint2 v1 = *(const uint2*)(base1 + OFF[t]);
            float2 g0 = __half22float2(*(__half2*)&v0.x);
            float2 g1 = __half22float2(*(__half2*)&v0.y);
            float2 h0 = __half22float2(*(__half2*)&v1.x);
            float2 h1 = __half22float2(*(__half2*)&v1.y);
            a0 += w0 * g0.x + w1 * h0.x;
            a1 += w0 * g0.y + w1 * h0.y;
            a2 += w0 * g1.x + w1 * h1.x;
            a3 += w0 * g1.y + w1 * h1.y;
        }
    }
    // tail edge
    if (i < end) {
        int p0 = g_epack[i];
        float wv = (lane < 8) ? g_bwc[(size_t)i * 8 + lane] : 0.0f;
        const __half* base0 = XWh + (size_t)(p0 & 0xffff) * NB2 + (size_t)(p0 >> 16) * CC + lane * 4;
#pragma unroll
        for (int t = 0; t < 8; t++) {
            float w0 = __shfl_sync(0xffffffffu, wv, t);
            uint2 v0 = *(const uint2*)(base0 + OFF[t]);
            float2 g0 = __half22float2(*(__half2*)&v0.x);
            float2 g1 = __half22float2(*(__half2*)&v0.y);
            a0 += w0 * g0.x;
            a1 += w0 * g0.y;
            a2 += w0 * g1.x;
            a3 += w0 * g1.y;
        }
    }

    if (doRelu) {
        a0 = fmaxf(a0, 0.f); a1 = fmaxf(a1, 0.f);
        a2 = fmaxf(a2, 0.f); a3 = fmaxf(a3, 0.f);
    }
    if (doOut)
        *(float4*)(out + (size_t)n * CC + lane * 4) = make_float4(a0, a1, a2, a3);

    if (doSplit) {
        float vv[4] = {a0, a1, a2, a3};
        __half hh[4], ll[4];
#pragma unroll
        for (int q = 0; q < 4; q++) {
            hh[q] = __float2half_rn(vv[q]);
            ll[q] = __float2half_rn(vv[q] - __half2float(hh[q]));
        }
        *(uint2*)(hi + (size_t)n * CC + lane * 4) = *(uint2*)hh;
        *(uint2*)(lo + (size_t)n * CC + lane * 4) = *(uint2*)ll;
    }
}

// ---------------- launch ----------------
extern "C" void kernel_launch(void* const* d_in, const int* in_sizes, int n_in,
                              void* d_out, int out_size) {
    const float* x    = (const float*)d_in[0];
    const void*  ei   = d_in[1];
    const float* ea   = (const float*)d_in[2];
    const float* Wp1  = (const float*)d_in[3];
    const float* bp1  = (const float*)d_in[4];
    const float* Wp2  = (const float*)d_in[5];
    const float* bp2  = (const float*)d_in[6];
    const float* W[3]  = {(const float*)d_in[7],  (const float*)d_in[10], (const float*)d_in[13]};
    const float* Wr[3] = {(const float*)d_in[8],  (const float*)d_in[11], (const float*)d_in[14]};
    const float* b[3]  = {(const float*)d_in[9],  (const float*)d_in[12], (const float*)d_in[15]};
    float* out_final = (float*)d_out;

    float* g_h_p;    cudaGetSymbolAddress((void**)&g_h_p, g_h);
    __half* xwh_p;   cudaGetSymbolAddress((void**)&xwh_p, g_XWh);
    __half* xhi_p;   cudaGetSymbolAddress((void**)&xhi_p, g_xhi);
    __half* xlo_p;   cudaGetSymbolAddress((void**)&xlo_p, g_xlo);
    __half* bt_p;    cudaGetSymbolAddress((void**)&bt_p, g_bt);

    cudaFuncSetAttribute(xw_hmma_kernel, cudaFuncAttributeMaxDynamicSharedMemorySize, SMEM_TOT);

    // 1) edge preprocessing + CSR build
    detect_idx_kernel<<<1, 32>>>((const unsigned int*)ei);
    zero_cnt_kernel<<<(NN + 255) / 256, 256>>>();
    edge_pre_kernel<<<(NE + 255) / 256, 256>>>(ei, ea, Wp1, bp1, Wp2, bp2);
    blocksum_kernel<<<SCAN_BLKS, 256>>>();
    scanpart_kernel<<<1, 128>>>();
    rowptr_kernel<<<SCAN_BLKS, 256>>>();
    scatter_kernel<<<(NE + 255) / 256, 256>>>();

    // 2) weights: transpose to fp16, root appended as block 27
    for (int l = 0; l < 3; l++) {
        conv_w_kernel<<<(KK * CC * CC + 255) / 256, 256>>>(W[l], bt_p + (size_t)l * NB2 * CC);
        conv_wr_kernel<<<(CC * CC + 255) / 256, 256>>>(Wr[l], bt_p + (size_t)l * NB2 * CC);
    }

    // 3) layer-0 activation split
    convert_act_kernel<<<(NN * CC + 255) / 256, 256>>>(x, xhi_p, xlo_p);

    // 4) three layers
    dim3 gridXW(NB2 / 128, (NN + 127) / 128);   // 28 x 157
    int aggBlocks = (NN + 7) / 8;

    for (int l = 0; l < 3; l++) {
        xw_hmma_kernel<<<gridXW, 256, SMEM_TOT>>>(
            xhi_p, xlo_p, bt_p + (size_t)l * NB2 * CC, xwh_p);

        // layers 0-1: only hi/lo split is consumed downstream; layer 2 writes d_out
        agg_csr_kernel<<<aggBlocks, 256>>>(
            xwh_p, b[l], (l == 2) ? out_final : g_h_p, xhi_p, xlo_p,
            /*doRelu=*/(l < 2) ? 1 : 0,
            /*doOut=*/(l == 2) ? 1 : 0,
            /*doSplit=*/(l < 2) ? 1 : 0);
    }
}

// round 15
// speedup vs baseline: 1.3116x; 1.0777x over previous
#include <cuda_runtime.h>
#include <cuda_fp16.h>
#include <math.h>
#include <stdint.h>

// Problem constants
#define NN   20000          // nodes
#define NE   320000         // edges
#define CC   128            // channels
#define KK   27             // kernel matrices
#define NB2  (28 * CC)      // 3584 = 27 kernel blocks + 1 root block
#define EDGE_DIM 16
#define MLP_HID  6
#define SCAN_BLKS 79        // 79*256 >= NN

// ---------------- static device scratch ----------------
__device__ int   g_idx64;
__device__ int   g_src[NE];
__device__ int   g_dst[NE];
__device__ int   g_kbase[NE];
__device__ float g_bw[NE * 8];           // edge-ordered
// CSR by dst
__device__ int   g_cnt[NN];
__device__ int   g_rowptr[NN + 1];
__device__ int   g_woff[NN];
__device__ int   g_bsum[SCAN_BLKS];
__device__ int   g_bpre[SCAN_BLKS];
__device__ int   g_epack[NE];            // src | (kbase<<16), CSR order
__device__ float g_bwc[NE * 8];          // bw, CSR order
// GEMM buffers
__device__ __half g_XWh[(size_t)NN * NB2];            // 143 MB fp16
__device__ float  g_h[NN * CC];
__device__ __half g_xhi[NN * CC];                     // activation hi (fp16)
__device__ __half g_xlo[NN * CC];                     // activation lo residual (fp16)
__device__ __half g_bt[3][(size_t)NB2 * CC];          // W^T fp16: [row=k*128+o][col=cin]

// ---------------- index width detection ----------------
__global__ void detect_idx_kernel(const unsigned int* __restrict__ ei) {
    if (blockIdx.x == 0 && threadIdx.x == 0) {
        int is64 = 1;
        for (int i = 0; i < 4096; i++) {
            if (ei[2 * i + 1] != 0u) { is64 = 0; break; }
        }
        g_idx64 = is64;
    }
}

__global__ void zero_cnt_kernel() {
    int i = blockIdx.x * blockDim.x + threadIdx.x;
    if (i < NN) g_cnt[i] = 0;
}

// ---------------- edge preprocessing ----------------
__global__ void edge_pre_kernel(const void* __restrict__ ei_raw,
                                const float* __restrict__ ea,
                                const float* __restrict__ Wp1,
                                const float* __restrict__ bp1,
                                const float* __restrict__ Wp2,
                                const float* __restrict__ bp2) {
    int e = blockIdx.x * blockDim.x + threadIdx.x;
    if (e >= NE) return;

    int s, d;
    if (g_idx64) {
        const long long* p = (const long long*)ei_raw;
        s = (int)p[e];
        d = (int)p[NE + e];
    } else {
        const int* p = (const int*)ei_raw;
        s = p[e];
        d = p[NE + e];
    }
    g_src[e] = s;
    g_dst[e] = d;
    atomicAdd(&g_cnt[d], 1);

    float a[EDGE_DIM];
#pragma unroll
    for (int i = 0; i < EDGE_DIM; i++) a[i] = ea[(size_t)e * EDGE_DIM + i];

    float h[MLP_HID];
#pragma unroll
    for (int j = 0; j < MLP_HID; j++) {
        float z = bp1[j];
#pragma unroll
        for (int i = 0; i < EDGE_DIM; i++) z += a[i] * Wp1[i * MLP_HID + j];
        h[j] = fmaxf(z, 0.0f);
    }

    float fr[3];
    int lo[3];
#pragma unroll
    for (int dd = 0; dd < 3; dd++) {
        float z = bp2[dd];
#pragma unroll
        for (int j = 0; j < MLP_HID; j++) z += h[j] * Wp2[j * 3 + dd];
        float u = 1.0f / (1.0f + expf(-z));
        float v = u * 2.0f;
        float l = fminf(fmaxf(floorf(v), 0.0f), 1.0f);
        lo[dd] = (int)l;
        fr[dd] = v - l;
    }
    g_kbase[e] = lo[0] + 3 * lo[1] + 9 * lo[2];

#pragma unroll
    for (int sb = 0; sb < 8; sb++) {
        float w = ((sb & 1) ? fr[0] : 1.0f - fr[0])
                * ((sb & 2) ? fr[1] : 1.0f - fr[1])
                * ((sb & 4) ? fr[2] : 1.0f - fr[2]);
        g_bw[(size_t)e * 8 + sb] = w;
    }
}

// ---------------- 3-phase scan ----------------
__global__ void blocksum_kernel() {
    __shared__ int sh[256];
    int idx = blockIdx.x * 256 + threadIdx.x;
    int c = (idx < NN) ? g_cnt[idx] : 0;
    sh[threadIdx.x] = c;
    __syncthreads();
    for (int s = 128; s > 0; s >>= 1) {
        if (threadIdx.x < s) sh[threadIdx.x] += sh[threadIdx.x + s];
        __syncthreads();
    }
    if (threadIdx.x == 0) g_bsum[blockIdx.x] = sh[0];
}

__global__ void scanpart_kernel() {
    __shared__ int sh[128];
    int t = threadIdx.x;
    int v = (t < SCAN_BLKS) ? g_bsum[t] : 0;
    sh[t] = v;
    __syncthreads();
    for (int d = 1; d < 128; d <<= 1) {
        int u = (t >= d) ? sh[t - d] : 0;
        __syncthreads();
        sh[t] += u;
        __syncthreads();
    }
    if (t < SCAN_BLKS) g_bpre[t] = sh[t] - v;
    if (t == 0) g_rowptr[NN] = NE;
}

__global__ void rowptr_kernel() {
    __shared__ int sh[256];
    int idx = blockIdx.x * 256 + threadIdx.x;
    int t = threadIdx.x;
    int c = (idx < NN) ? g_cnt[idx] : 0;
    sh[t] = c;
    __syncthreads();
    for (int d = 1; d < 256; d <<= 1) {
        int u = (t >= d) ? sh[t - d] : 0;
        __syncthreads();
        sh[t] += u;
        __syncthreads();
    }
    if (idx < NN) {
        int excl = g_bpre[blockIdx.x] + sh[t] - c;
        g_rowptr[idx] = excl;
        g_woff[idx] = excl;
    }
}

__global__ void scatter_kernel() {
    int e = blockIdx.x * blockDim.x + threadIdx.x;
    if (e >= NE) return;
    int d = g_dst[e];
    int pos = atomicAdd(&g_woff[d], 1);
    g_epack[pos] = g_src[e] | (g_kbase[e] << 16);
#pragma unroll
    for (int t = 0; t < 8; t++) g_bwc[(size_t)pos * 8 + t] = g_bw[(size_t)e * 8 + t];
}

// -------- W [nk,Cin,H] fp32 -> Bt rows [(kbase+k)*H+o], cols [Cin] fp16 --------
// shared-tile transpose: coalesced loads, 64B-contiguous stores.
// grid: (nk, 4); block 256. Each block: k = blockIdx.x, i-chunk = blockIdx.y (32 rows).
__global__ void conv_w_kernel(const float* __restrict__ W, __half* __restrict__ bt, int kbase) {
    __shared__ float tile[32][129];
    const int k = blockIdx.x;
    const int chunk = blockIdx.y;
#pragma unroll
    for (int it = 0; it < 16; it++) {
        int idx = it * 256 + threadIdx.x;     // 0..4095
        int r = idx >> 7, o = idx & 127;      // r: i-row within chunk, o: out-channel
        tile[r][o] = W[((size_t)k * 128 + chunk * 32 + r) * 128 + o];
    }
    __syncthreads();
#pragma unroll
    for (int it = 0; it < 16; it++) {
        int idx = it * 256 + threadIdx.x;
        int o = idx >> 5, i = idx & 31;
        bt[(size_t)((kbase + k) * 128 + o) * 128 + chunk * 32 + i] =
            __float2half_rn(tile[i][o]);
    }
}

// -------- activation fp32 -> fp16 hi/lo split (layer 0 only) --------
__global__ void convert_act_kernel(const float* __restrict__ a,
                                   __half* __restrict__ hi,
                                   __half* __restrict__ lo) {
    int i = blockIdx.x * blockDim.x + threadIdx.x;
    if (i >= NN * CC) return;
    float v = a[i];
    __half h = __float2half_rn(v);
    hi[i] = h;
    lo[i] = __float2half_rn(v - __half2float(h));
}

// ================= HMMA (mma.sync fp16) 2-pass GEMM: XWh = act @ Bt^T =================
#define SM_AHI 0
#define SM_ALO 32768
#define SM_B   65536
#define SMEM_TOT 98304

__device__ __forceinline__ uint32_t smem_u32(const void* p) {
    uint32_t a;
    asm("{ .reg .u64 t; cvta.to.shared.u64 t, %1; cvt.u32.u64 %0, t; }" : "=r"(a) : "l"(p));
    return a;
}
__device__ __forceinline__ uint32_t sw_off(int row, int kc) {
    return (uint32_t)(row * 256 + ((kc ^ (row & 7)) << 4));
}
__device__ __forceinline__ void load_tile(char* smem, int off,
                                          const __half* __restrict__ src,
                                          int row_base, int row_max, int tid) {
#pragma unroll
    for (int it = 0; it < 8; it++) {
        int idx = it * 256 + tid;
        int row = idx >> 4, kc = idx & 15;
        int grow = row_base + row;
        uint4 v = make_uint4(0u, 0u, 0u, 0u);
        if (grow < row_max)
            v = *(const uint4*)(src + (size_t)grow * CC + kc * 8);
        *(uint4*)(smem + off + sw_off(row, kc)) = v;
    }
}
__device__ __forceinline__ void ldmatrix_x4(uint32_t* r, uint32_t addr) {
    asm volatile("ldmatrix.sync.aligned.m8n8.x4.shared.b16 {%0,%1,%2,%3}, [%4];"
                 : "=r"(r[0]), "=r"(r[1]), "=r"(r[2]), "=r"(r[3]) : "r"(addr));
}
__device__ __forceinline__ void mma16816(float* c, const uint32_t* a, const uint32_t* b) {
    asm volatile(
        "mma.sync.aligned.m16n8k16.row.col.f32.f16.f16.f32 "
        "{%0,%1,%2,%3}, {%4,%5,%6,%7}, {%8,%9}, {%0,%1,%2,%3};"
        : "+f"(c[0]), "+f"(c[1]), "+f"(c[2]), "+f"(c[3])
        : "r"(a[0]), "r"(a[1]), "r"(a[2]), "r"(a[3]), "r"(b[0]), "r"(b[1]));
}

__global__ void __launch_bounds__(256, 2)
xw_hmma_kernel(const __half* __restrict__ xhi,
               const __half* __restrict__ xlo,
               const __half* __restrict__ bt,
               __half* __restrict__ XWh) {
    extern __shared__ __align__(1024) char smem[];
    const int tid  = threadIdx.x;
    const int wid  = tid >> 5;
    const int lane = tid & 31;
    const int bn = blockIdx.x * 128;
    const int bm = blockIdx.y * 128;

    load_tile(smem, SM_AHI, xhi, bm, NN, tid);
    load_tile(smem, SM_B,   bt,  bn, NB2, tid);
    load_tile(smem, SM_ALO, xlo, bm, NN, tid);
    __syncthreads();

    const uint32_t sbase = smem_u32(smem);
    const int m_base = (wid & 1) * 64;
    const int n_base = (wid >> 1) * 32;

    float acc[4][4][4];
#pragma unroll
    for (int mt = 0; mt < 4; mt++)
#pragma unroll
        for (int nt = 0; nt < 4; nt++)
#pragma unroll
            for (int q = 0; q < 4; q++) acc[mt][nt][q] = 0.0f;

    const int a_row_in = (lane & 15);
    const int a_kadd   = (lane >> 4);
    const int b_row_in = ((lane >> 4) << 3) + (lane & 7);
    const int b_kadd   = ((lane >> 3) & 1);

    auto run_pass = [&](int offA) {
        const uint32_t abase = sbase + offA;
        const uint32_t bbase = sbase + SM_B;
#pragma unroll
        for (int ks = 0; ks < 8; ks++) {
            const int kc = ks * 2;
            uint32_t afrag[4][4];
#pragma unroll
            for (int mt = 0; mt < 4; mt++) {
                int row = m_base + mt * 16 + a_row_in;
                ldmatrix_x4(afrag[mt], abase + sw_off(row, kc + a_kadd));
            }
            uint32_t bfrag[4][2];
#pragma unroll
            for (int g = 0; g < 2; g++) {
                uint32_t r[4];
                int nrow = n_base + g * 16 + b_row_in;
                ldmatrix_x4(r, bbase + sw_off(nrow, kc + b_kadd));
                bfrag[2 * g][0]     = r[0];
                bfrag[2 * g][1]     = r[1];
                bfrag[2 * g + 1][0] = r[2];
                bfrag[2 * g + 1][1] = r[3];
            }
#pragma unroll
            for (int mt = 0; mt < 4; mt++)
#pragma unroll
                for (int nt = 0; nt < 4; nt++)
                    mma16816(acc[mt][nt], afrag[mt], bfrag[nt]);
        }
    };

    run_pass(SM_AHI);   // Ahi * B
    run_pass(SM_ALO);   // Alo * B

    // epilogue: fp16 store
    const int qrow = lane >> 2;
    const int qcol = (lane & 3) * 2;
#pragma unroll
    for (int mt = 0; mt < 4; mt++) {
        int r0 = bm + m_base + mt * 16 + qrow;
        int r1 = r0 + 8;
#pragma unroll
        for (int nt = 0; nt < 4; nt++) {
            int col = bn + n_base + nt * 8 + qcol;
            if (r0 < NN) {
                __half2 h = __floats2half2_rn(acc[mt][nt][0], acc[mt][nt][1]);
                *(uint32_t*)(XWh + (size_t)r0 * NB2 + col) = *(uint32_t*)&h;
            }
            if (r1 < NN) {
                __half2 h = __floats2half2_rn(acc[mt][nt][2], acc[mt][nt][3]);
                *(uint32_t*)(XWh + (size_t)r1 * NB2 + col) = *(uint32_t*)&h;
            }
        }
    }
}

// ======== fused aggregation: bias + root + edges, 4-edge software pipeline ========
__global__ void __launch_bounds__(256)
agg_csr_kernel(const __half* __restrict__ XWh,
               const float* __restrict__ bias,
               float* __restrict__ out,
               __half* __restrict__ hi,
               __half* __restrict__ lo,
               int doRelu, int doOut, int doSplit) {
    const int n = blockIdx.x * 8 + (threadIdx.x >> 5);
    const int lane = threadIdx.x & 31;
    if (n >= NN) return;
    const int OFF[8] = {0, 128, 384, 512, 1152, 1280, 1536, 1664};  // {0,1,3,4,9,10,12,13}*CC

    float4 bb = *(const float4*)(bias + lane * 4);
    float a0 = bb.x, a1 = bb.y, a2 = bb.z, a3 = bb.w;
    {
        uint2 v = *(const uint2*)(XWh + (size_t)n * NB2 + 27 * CC + lane * 4);
        float2 f0 = __half22float2(*(__half2*)&v.x);
        float2 f1 = __half22float2(*(__half2*)&v.y);
        a0 += f0.x; a1 += f0.y; a2 += f1.x; a3 += f1.y;
    }

    const int beg = g_rowptr[n];
    const int end = g_rowptr[n + 1];
    int i = beg;
    // 4-edge pipelined main loop: one 128B bw read (all 32 lanes) serves 4 edges
    for (; i + 4 <= end; i += 4) {
        int p0 = g_epack[i];
        int p1 = g_epack[i + 1];
        int p2 = g_epack[i + 2];
        int p3 = g_epack[i + 3];
        float wv = g_bwc[(size_t)i * 8 + lane];
        const __half* base0 = XWh + (size_t)(p0 & 0xffff) * NB2 + (size_t)(p0 >> 16) * CC + lane * 4;
        const __half* base1 = XWh + (size_t)(p1 & 0xffff) * NB2 + (size_t)(p1 >> 16) * CC + lane * 4;
        const __half* base2 = XWh + (size_t)(p2 & 0xffff) * NB2 + (size_t)(p2 >> 16) * CC + lane * 4;
        const __half* base3 = XWh + (size_t)(p3 & 0xffff) * NB2 + (size_t)(p3 >> 16) * CC + lane * 4;
#pragma unroll
        for (int t = 0; t < 8; t++) {
            float w0 = __shfl_sync(0xffffffffu, wv, t);
            float w1 = __shfl_sync(0xffffffffu, wv, t + 8);
            float w2 = __shfl_sync(0xffffffffu, wv, t + 16);
            float w3 = __shfl_sync(0xffffffffu, wv, t + 24);
            uint2 v0 = *(const uint2*)(base0 + OFF[t]);
            uint2 v1 = *(const uint2*)(base1 + OFF[t]);
            uint2 v2 = *(const uint2*)(base2 + OFF[t]);
            uint2 v3 = *(const uint2*)(base3 + OFF[t]);
            float2 e0a = __half22float2(*(__half2*)&v0.x);
            float2 e0b = __half22float2(*(__half2*)&v0.y);
            float2 e1a = __half22float2(*(__half2*)&v1.x);
            float2 e1b = __half22float2(*(__half2*)&v1.y);
            float2 e2a = __half22float2(*(__half2*)&v2.x);
            float2 e2b = __half22float2(*(__half2*)&v2.y);
            float2 e3a = __half22float2(*(__half2*)&v3.x);
            float2 e3b = __half22float2(*(__half2*)&v3.y);
            a0 += w0 * e0a.x + w1 * e1a.x + w2 * e2a.x + w3 * e3a.x;
            a1 += w0 * e0a.y + w1 * e1a.y + w2 * e2a.y + w3 * e3a.y;
            a2 += w0 * e0b.x + w1 * e1b.x + w2 * e2b.x + w3 * e3b.x;
            a3 += w0 * e0b.y + w1 * e1b.y + w2 * e2b.y + w3 * e3b.y;
        }
    }
    // tail edges (0-3)
    for (; i < end; i++) {
        int p0 = g_epack[i];
        float wv = (lane < 8) ? g_bwc[(size_t)i * 8 + lane] : 0.0f;
        const __half* base0 = XWh + (size_t)(p0 & 0xffff) * NB2 + (size_t)(p0 >> 16) * CC + lane * 4;
#pragma unroll
        for (int t = 0; t < 8; t++) {
            float w0 = __shfl_sync(0xffffffffu, wv, t);
            uint2 v0 = *(const uint2*)(base0 + OFF[t]);
            float2 g0 = __half22float2(*(__half2*)&v0.x);
            float2 g1 = __half22float2(*(__half2*)&v0.y);
            a0 += w0 * g0.x;
            a1 += w0 * g0.y;
            a2 += w0 * g1.x;
            a3 += w0 * g1.y;
        }
    }

    if (doRelu) {
        a0 = fmaxf(a0, 0.f); a1 = fmaxf(a1, 0.f);
        a2 = fmaxf(a2, 0.f); a3 = fmaxf(a3, 0.f);
    }
    if (doOut)
        *(float4*)(out + (size_t)n * CC + lane * 4) = make_float4(a0, a1, a2, a3);

    if (doSplit) {
        float vv[4] = {a0, a1, a2, a3};
        __half hh[4], ll[4];
#pragma unroll
        for (int q = 0; q < 4; q++) {
            hh[q] = __float2half_rn(vv[q]);
            ll[q] = __float2half_rn(vv[q] - __half2float(hh[q]));
        }
        *(uint2*)(hi + (size_t)n * CC + lane * 4) = *(uint2*)hh;
        *(uint2*)(lo + (size_t)n * CC + lane * 4) = *(uint2*)ll;
    }
}

// ---------------- launch ----------------
extern "C" void kernel_launch(void* const* d_in, const int* in_sizes, int n_in,
                              void* d_out, int out_size) {
    const float* x    = (const float*)d_in[0];
    const void*  ei   = d_in[1];
    const float* ea   = (const float*)d_in[2];
    const float* Wp1  = (const float*)d_in[3];
    const float* bp1  = (const float*)d_in[4];
    const float* Wp2  = (const float*)d_in[5];
    const float* bp2  = (const float*)d_in[6];
    const float* W[3]  = {(const float*)d_in[7],  (const float*)d_in[10], (const float*)d_in[13]};
    const float* Wr[3] = {(const float*)d_in[8],  (const float*)d_in[11], (const float*)d_in[14]};
    const float* b[3]  = {(const float*)d_in[9],  (const float*)d_in[12], (const float*)d_in[15]};
    float* out_final = (float*)d_out;

    float* g_h_p;    cudaGetSymbolAddress((void**)&g_h_p, g_h);
    __half* xwh_p;   cudaGetSymbolAddress((void**)&xwh_p, g_XWh);
    __half* xhi_p;   cudaGetSymbolAddress((void**)&xhi_p, g_xhi);
    __half* xlo_p;   cudaGetSymbolAddress((void**)&xlo_p, g_xlo);
    __half* bt_p;    cudaGetSymbolAddress((void**)&bt_p, g_bt);

    cudaFuncSetAttribute(xw_hmma_kernel, cudaFuncAttributeMaxDynamicSharedMemorySize, SMEM_TOT);

    // 1) edge preprocessing + CSR build
    detect_idx_kernel<<<1, 32>>>((const unsigned int*)ei);
    zero_cnt_kernel<<<(NN + 255) / 256, 256>>>();
    edge_pre_kernel<<<(NE + 255) / 256, 256>>>(ei, ea, Wp1, bp1, Wp2, bp2);
    blocksum_kernel<<<SCAN_BLKS, 256>>>();
    scanpart_kernel<<<1, 128>>>();
    rowptr_kernel<<<SCAN_BLKS, 256>>>();
    scatter_kernel<<<(NE + 255) / 256, 256>>>();

    // 2) weights: shared-tile transpose to fp16, root appended as block 27
    for (int l = 0; l < 3; l++) {
        conv_w_kernel<<<dim3(KK, 4), 256>>>(W[l], bt_p + (size_t)l * NB2 * CC, 0);
        conv_w_kernel<<<dim3(1, 4), 256>>>(Wr[l], bt_p + (size_t)l * NB2 * CC, 27);
    }

    // 3) layer-0 activation split
    convert_act_kernel<<<(NN * CC + 255) / 256, 256>>>(x, xhi_p, xlo_p);

    // 4) three layers
    dim3 gridXW(NB2 / 128, (NN + 127) / 128);   // 28 x 157
    int aggBlocks = (NN + 7) / 8;

    for (int l = 0; l < 3; l++) {
        xw_hmma_kernel<<<gridXW, 256, SMEM_TOT>>>(
            xhi_p, xlo_p, bt_p + (size_t)l * NB2 * CC, xwh_p);

        agg_csr_kernel<<<aggBlocks, 256>>>(
            xwh_p, b[l], (l == 2) ? out_final : g_h_p, xhi_p, xlo_p,
            /*doRelu=*/(l < 2) ? 1 : 0,
            /*doOut=*/(l == 2) ? 1 : 0,
            /*doSplit=*/(l < 2) ? 1 : 0);
    }
}

// round 16
// speedup vs baseline: 1.3969x; 1.0650x over previous
#include <cuda_runtime.h>
#include <cuda_fp16.h>
#include <math.h>
#include <stdint.h>

// Problem constants
#define NN   20000          // nodes
#define NE   320000         // edges
#define CC   128            // channels
#define KK   27             // kernel matrices
#define NB2  (28 * CC)      // 3584 = 27 kernel blocks + 1 root block
#define EDGE_DIM 16
#define MLP_HID  6
#define SCAN_BLKS 79        // 79*256 >= NN

// ---------------- static device scratch ----------------
__device__ int   g_idx64;
// CSR by dst
__device__ int   g_cnt[NN];
__device__ int   g_rowptr[NN + 1];
__device__ int   g_woff[NN];
__device__ int   g_bsum[SCAN_BLKS];
__device__ int   g_bpre[SCAN_BLKS];
__device__ int   g_epack[NE];            // src | (kbase<<16), CSR order
__device__ float g_bwc[NE * 8];          // bw, CSR order
// GEMM buffers
__device__ __half g_XWh[(size_t)NN * NB2];            // 143 MB fp16
__device__ __half g_xhi[NN * CC];                     // activation hi (fp16)
__device__ __half g_xlo[NN * CC];                     // activation lo residual (fp16)
__device__ __half g_bt[3][(size_t)NB2 * CC];          // W^T fp16: [row=k*128+o][col=cin]

// ---------------- index width detection ----------------
__global__ void detect_idx_kernel(const unsigned int* __restrict__ ei) {
    if (blockIdx.x == 0 && threadIdx.x == 0) {
        int is64 = 1;
        for (int i = 0; i < 4096; i++) {
            if (ei[2 * i + 1] != 0u) { is64 = 0; break; }
        }
        g_idx64 = is64;
    }
}

__global__ void zero_cnt_kernel() {
    int i = blockIdx.x * blockDim.x + threadIdx.x;
    if (i < NN) g_cnt[i] = 0;
}

// ---------------- pass 1: count edges per dst ----------------
__global__ void count_kernel(const void* __restrict__ ei_raw) {
    int e = blockIdx.x * blockDim.x + threadIdx.x;
    if (e >= NE) return;
    int d;
    if (g_idx64) d = (int)((const long long*)ei_raw)[NE + e];
    else         d = ((const int*)ei_raw)[NE + e];
    atomicAdd(&g_cnt[d], 1);
}

// ---------------- 3-phase scan ----------------
__global__ void blocksum_kernel() {
    __shared__ int sh[256];
    int idx = blockIdx.x * 256 + threadIdx.x;
    int c = (idx < NN) ? g_cnt[idx] : 0;
    sh[threadIdx.x] = c;
    __syncthreads();
    for (int s = 128; s > 0; s >>= 1) {
        if (threadIdx.x < s) sh[threadIdx.x] += sh[threadIdx.x + s];
        __syncthreads();
    }
    if (threadIdx.x == 0) g_bsum[blockIdx.x] = sh[0];
}

__global__ void scanpart_kernel() {
    __shared__ int sh[128];
    int t = threadIdx.x;
    int v = (t < SCAN_BLKS) ? g_bsum[t] : 0;
    sh[t] = v;
    __syncthreads();
    for (int d = 1; d < 128; d <<= 1) {
        int u = (t >= d) ? sh[t - d] : 0;
        __syncthreads();
        sh[t] += u;
        __syncthreads();
    }
    if (t < SCAN_BLKS) g_bpre[t] = sh[t] - v;
    if (t == 0) g_rowptr[NN] = NE;
}

__global__ void rowptr_kernel() {
    __shared__ int sh[256];
    int idx = blockIdx.x * 256 + threadIdx.x;
    int t = threadIdx.x;
    int c = (idx < NN) ? g_cnt[idx] : 0;
    sh[t] = c;
    __syncthreads();
    for (int d = 1; d < 256; d <<= 1) {
        int u = (t >= d) ? sh[t - d] : 0;
        __syncthreads();
        sh[t] += u;
        __syncthreads();
    }
    if (idx < NN) {
        int excl = g_bpre[blockIdx.x] + sh[t] - c;
        g_rowptr[idx] = excl;
        g_woff[idx] = excl;
    }
}

// ---------------- pass 2: fused MLP + spline basis + direct CSR write ----------------
__global__ void edge_csr_kernel(const void* __restrict__ ei_raw,
                                const float* __restrict__ ea,
                                const float* __restrict__ Wp1,
                                const float* __restrict__ bp1,
                                const float* __restrict__ Wp2,
                                const float* __restrict__ bp2) {
    int e = blockIdx.x * blockDim.x + threadIdx.x;
    if (e >= NE) return;

    int s, d;
    if (g_idx64) {
        const long long* p = (const long long*)ei_raw;
        s = (int)p[e];
        d = (int)p[NE + e];
    } else {
        const int* p = (const int*)ei_raw;
        s = p[e];
        d = p[NE + e];
    }

    float a[EDGE_DIM];
#pragma unroll
    for (int i = 0; i < EDGE_DIM; i++) a[i] = ea[(size_t)e * EDGE_DIM + i];

    float h[MLP_HID];
#pragma unroll
    for (int j = 0; j < MLP_HID; j++) {
        float z = bp1[j];
#pragma unroll
        for (int i = 0; i < EDGE_DIM; i++) z += a[i] * Wp1[i * MLP_HID + j];
        h[j] = fmaxf(z, 0.0f);
    }

    float fr[3];
    int lo[3];
#pragma unroll
    for (int dd = 0; dd < 3; dd++) {
        float z = bp2[dd];
#pragma unroll
        for (int j = 0; j < MLP_HID; j++) z += h[j] * Wp2[j * 3 + dd];
        float u = 1.0f / (1.0f + expf(-z));
        float v = u * 2.0f;
        float l = fminf(fmaxf(floorf(v), 0.0f), 1.0f);
        lo[dd] = (int)l;
        fr[dd] = v - l;
    }
    int kb = lo[0] + 3 * lo[1] + 9 * lo[2];

    int pos = atomicAdd(&g_woff[d], 1);
    g_epack[pos] = s | (kb << 16);
#pragma unroll
    for (int sb = 0; sb < 8; sb++) {
        float w = ((sb & 1) ? fr[0] : 1.0f - fr[0])
                * ((sb & 2) ? fr[1] : 1.0f - fr[1])
                * ((sb & 4) ? fr[2] : 1.0f - fr[2]);
        g_bwc[(size_t)pos * 8 + sb] = w;
    }
}

// -------- W [nk,Cin,H] fp32 -> Bt rows [(kbase+k)*H+o], cols [Cin] fp16 --------
__global__ void conv_w_kernel(const float* __restrict__ W, __half* __restrict__ bt, int kbase) {
    __shared__ float tile[32][129];
    const int k = blockIdx.x;
    const int chunk = blockIdx.y;
#pragma unroll
    for (int it = 0; it < 16; it++) {
        int idx = it * 256 + threadIdx.x;
        int r = idx >> 7, o = idx & 127;
        tile[r][o] = W[((size_t)k * 128 + chunk * 32 + r) * 128 + o];
    }
    __syncthreads();
#pragma unroll
    for (int it = 0; it < 16; it++) {
        int idx = it * 256 + threadIdx.x;
        int o = idx >> 5, i = idx & 31;
        bt[(size_t)((kbase + k) * 128 + o) * 128 + chunk * 32 + i] =
            __float2half_rn(tile[i][o]);
    }
}

// -------- activation fp32 -> fp16 hi/lo split (layer 0 only) --------
__global__ void convert_act_kernel(const float* __restrict__ a,
                                   __half* __restrict__ hi,
                                   __half* __restrict__ lo) {
    int i = blockIdx.x * blockDim.x + threadIdx.x;
    if (i >= NN * CC) return;
    float v = a[i];
    __half h = __float2half_rn(v);
    hi[i] = h;
    lo[i] = __float2half_rn(v - __half2float(h));
}

// ================= HMMA (mma.sync fp16) 2-pass GEMM: XWh = act @ Bt^T =================
#define SM_AHI 0
#define SM_ALO 32768
#define SM_B   65536
#define SMEM_TOT 98304

__device__ __forceinline__ uint32_t smem_u32(const void* p) {
    uint32_t a;
    asm("{ .reg .u64 t; cvta.to.shared.u64 t, %1; cvt.u32.u64 %0, t; }" : "=r"(a) : "l"(p));
    return a;
}
__device__ __forceinline__ uint32_t sw_off(int row, int kc) {
    return (uint32_t)(row * 256 + ((kc ^ (row & 7)) << 4));
}
__device__ __forceinline__ void load_tile(char* smem, int off,
                                          const __half* __restrict__ src,
                                          int row_base, int row_max, int tid) {
#pragma unroll
    for (int it = 0; it < 8; it++) {
        int idx = it * 256 + tid;
        int row = idx >> 4, kc = idx & 15;
        int grow = row_base + row;
        uint4 v = make_uint4(0u, 0u, 0u, 0u);
        if (grow < row_max)
            v = *(const uint4*)(src + (size_t)grow * CC + kc * 8);
        *(uint4*)(smem + off + sw_off(row, kc)) = v;
    }
}
__device__ __forceinline__ void ldmatrix_x4(uint32_t* r, uint32_t addr) {
    asm volatile("ldmatrix.sync.aligned.m8n8.x4.shared.b16 {%0,%1,%2,%3}, [%4];"
                 : "=r"(r[0]), "=r"(r[1]), "=r"(r[2]), "=r"(r[3]) : "r"(addr));
}
__device__ __forceinline__ void mma16816(float* c, const uint32_t* a, const uint32_t* b) {
    asm volatile(
        "mma.sync.aligned.m16n8k16.row.col.f32.f16.f16.f32 "
        "{%0,%1,%2,%3}, {%4,%5,%6,%7}, {%8,%9}, {%0,%1,%2,%3};"
        : "+f"(c[0]), "+f"(c[1]), "+f"(c[2]), "+f"(c[3])
        : "r"(a[0]), "r"(a[1]), "r"(a[2]), "r"(a[3]), "r"(b[0]), "r"(b[1]));
}

__global__ void __launch_bounds__(256, 2)
xw_hmma_kernel(const __half* __restrict__ xhi,
               const __half* __restrict__ xlo,
               const __half* __restrict__ bt,
               __half* __restrict__ XWh) {
    extern __shared__ __align__(1024) char smem[];
    const int tid  = threadIdx.x;
    const int wid  = tid >> 5;
    const int lane = tid & 31;
    const int bn = blockIdx.x * 128;
    const int bm = blockIdx.y * 128;

    load_tile(smem, SM_AHI, xhi, bm, NN, tid);
    load_tile(smem, SM_B,   bt,  bn, NB2, tid);
    load_tile(smem, SM_ALO, xlo, bm, NN, tid);
    __syncthreads();

    const uint32_t sbase = smem_u32(smem);
    const int m_base = (wid & 1) * 64;
    const int n_base = (wid >> 1) * 32;

    float acc[4][4][4];
#pragma unroll
    for (int mt = 0; mt < 4; mt++)
#pragma unroll
        for (int nt = 0; nt < 4; nt++)
#pragma unroll
            for (int q = 0; q < 4; q++) acc[mt][nt][q] = 0.0f;

    const int a_row_in = (lane & 15);
    const int a_kadd   = (lane >> 4);
    const int b_row_in = ((lane >> 4) << 3) + (lane & 7);
    const int b_kadd   = ((lane >> 3) & 1);

    auto run_pass = [&](int offA) {
        const uint32_t abase = sbase + offA;
        const uint32_t bbase = sbase + SM_B;
#pragma unroll
        for (int ks = 0; ks < 8; ks++) {
            const int kc = ks * 2;
            uint32_t afrag[4][4];
#pragma unroll
            for (int mt = 0; mt < 4; mt++) {
                int row = m_base + mt * 16 + a_row_in;
                ldmatrix_x4(afrag[mt], abase + sw_off(row, kc + a_kadd));
            }
            uint32_t bfrag[4][2];
#pragma unroll
            for (int g = 0; g < 2; g++) {
                uint32_t r[4];
                int nrow = n_base + g * 16 + b_row_in;
                ldmatrix_x4(r, bbase + sw_off(nrow, kc + b_kadd));
                bfrag[2 * g][0]     = r[0];
                bfrag[2 * g][1]     = r[1];
                bfrag[2 * g + 1][0] = r[2];
                bfrag[2 * g + 1][1] = r[3];
            }
#pragma unroll
            for (int mt = 0; mt < 4; mt++)
#pragma unroll
                for (int nt = 0; nt < 4; nt++)
                    mma16816(acc[mt][nt], afrag[mt], bfrag[nt]);
        }
    };

    run_pass(SM_AHI);   // Ahi * B
    run_pass(SM_ALO);   // Alo * B

    // epilogue: fp16 store
    const int qrow = lane >> 2;
    const int qcol = (lane & 3) * 2;
#pragma unroll
    for (int mt = 0; mt < 4; mt++) {
        int r0 = bm + m_base + mt * 16 + qrow;
        int r1 = r0 + 8;
#pragma unroll
        for (int nt = 0; nt < 4; nt++) {
            int col = bn + n_base + nt * 8 + qcol;
            if (r0 < NN) {
                __half2 h = __floats2half2_rn(acc[mt][nt][0], acc[mt][nt][1]);
                *(uint32_t*)(XWh + (size_t)r0 * NB2 + col) = *(uint32_t*)&h;
            }
            if (r1 < NN) {
                __half2 h = __floats2half2_rn(acc[mt][nt][2], acc[mt][nt][3]);
                *(uint32_t*)(XWh + (size_t)r1 * NB2 + col) = *(uint32_t*)&h;
            }
        }
    }
}

// ======== fused aggregation: tap-pair uint4 gathers, 4-edge pipeline ========
// Taps pair into adjacent blocks {0,1},{3,4},{9,10},{12,13}: one 512B segment each.
// Lane l reads 8 halfs at (kb+pb)*128 + l*8 : lanes 0-15 = even tap, 16-31 = odd tap.
// Each lane accumulates 8 channels; phases merged at the end via shfl_down 16.
__global__ void __launch_bounds__(256)
agg_csr_kernel(const __half* __restrict__ XWh,
               const float* __restrict__ bias,
               float* __restrict__ out,
               __half* __restrict__ hi,
               __half* __restrict__ lo,
               int doRelu, int doOut, int doSplit) {
    const int n = blockIdx.x * 8 + (threadIdx.x >> 5);
    const int lane = threadIdx.x & 31;
    if (n >= NN) return;
    const int POFF[4] = {0, 384, 1152, 1536};  // {0,3,9,12}*128 halfs
    const int phase = lane >> 4;               // 0: even tap of pair, 1: odd tap
    const int loff  = lane * 8;                // half offset within 512B pair segment

    float acc[8];
#pragma unroll
    for (int q = 0; q < 8; q++) acc[q] = 0.0f;

    const int beg = g_rowptr[n];
    const int end = g_rowptr[n + 1];
    int i = beg;
    for (; i + 4 <= end; i += 4) {
        int p0 = g_epack[i];
        int p1 = g_epack[i + 1];
        int p2 = g_epack[i + 2];
        int p3 = g_epack[i + 3];
        float wv = g_bwc[(size_t)i * 8 + lane];
        const __half* b0 = XWh + (size_t)(p0 & 0xffff) * NB2 + (size_t)(p0 >> 16) * CC + loff;
        const __half* b1 = XWh + (size_t)(p1 & 0xffff) * NB2 + (size_t)(p1 >> 16) * CC + loff;
        const __half* b2 = XWh + (size_t)(p2 & 0xffff) * NB2 + (size_t)(p2 >> 16) * CC + loff;
        const __half* b3 = XWh + (size_t)(p3 & 0xffff) * NB2 + (size_t)(p3 >> 16) * CC + loff;
#pragma unroll
        for (int p = 0; p < 4; p++) {
            int ts = 2 * p + phase;
            float w0 = __shfl_sync(0xffffffffu, wv, ts);
            float w1 = __shfl_sync(0xffffffffu, wv, 8 + ts);
            float w2 = __shfl_sync(0xffffffffu, wv, 16 + ts);
            float w3 = __shfl_sync(0xffffffffu, wv, 24 + ts);
            uint4 v0 = *(const uint4*)(b0 + POFF[p]);
            uint4 v1 = *(const uint4*)(b1 + POFF[p]);
            uint4 v2 = *(const uint4*)(b2 + POFF[p]);
            uint4 v3 = *(const uint4*)(b3 + POFF[p]);
            const uint32_t* u0 = &v0.x;
            const uint32_t* u1 = &v1.x;
            const uint32_t* u2 = &v2.x;
            const uint32_t* u3 = &v3.x;
#pragma unroll
            for (int j = 0; j < 4; j++) {
                float2 f0 = __half22float2(*(const __half2*)&u0[j]);
                float2 f1 = __half22float2(*(const __half2*)&u1[j]);
                float2 f2 = __half22float2(*(const __half2*)&u2[j]);
                float2 f3 = __half22float2(*(const __half2*)&u3[j]);
                acc[2 * j]     += w0 * f0.x + w1 * f1.x + w2 * f2.x + w3 * f3.x;
                acc[2 * j + 1] += w0 * f0.y + w1 * f1.y + w2 * f2.y + w3 * f3.y;
            }
        }
    }
    // tail edges (0-3)
    for (; i < end; i++) {
        int p0 = g_epack[i];
        float wv = (lane < 8) ? g_bwc[(size_t)i * 8 + lane] : 0.0f;
        const __half* b0 = XWh + (size_t)(p0 & 0xffff) * NB2 + (size_t)(p0 >> 16) * CC + loff;
#pragma unroll
        for (int p = 0; p < 4; p++) {
            float w0 = __shfl_sync(0xffffffffu, wv, 2 * p + phase);
            uint4 v0 = *(const uint4*)(b0 + POFF[p]);
            const uint32_t* u0 = &v0.x;
#pragma unroll
            for (int j = 0; j < 4; j++) {
                float2 f0 = __half22float2(*(const __half2*)&u0[j]);
                acc[2 * j]     += w0 * f0.x;
                acc[2 * j + 1] += w0 * f0.y;
            }
        }
    }

    // merge phases: lane L (<16) gets odd-tap partial from lane L+16
#pragma unroll
    for (int q = 0; q < 8; q++)
        acc[q] += __shfl_down_sync(0xffffffffu, acc[q], 16);

    if (lane < 16) {
        // bias + root block (tap 27 of own node), channels lane*8 .. +7
        uint4 rv = *(const uint4*)(XWh + (size_t)n * NB2 + 27 * CC + loff);
        const uint32_t* ru = &rv.x;
        float4 bb0 = *(const float4*)(bias + loff);
        float4 bb1 = *(const float4*)(bias + loff + 4);
        const float* bp = &bb0.x;
        float res[8];
#pragma unroll
        for (int j = 0; j < 4; j++) {
            float2 f = __half22float2(*(const __half2*)&ru[j]);
            res[2 * j]     = acc[2 * j]     + f.x;
            res[2 * j + 1] = acc[2 * j + 1] + f.y;
        }
        res[0] += bb0.x; res[1] += bb0.y; res[2] += bb0.z; res[3] += bb0.w;
        res[4] += bb1.x; res[5] += bb1.y; res[6] += bb1.z; res[7] += bb1.w;
        (void)bp;

        if (doRelu) {
#pragma unroll
            for (int q = 0; q < 8; q++) res[q] = fmaxf(res[q], 0.0f);
        }
        if (doOut) {
            *(float4*)(out + (size_t)n * CC + loff)     = make_float4(res[0], res[1], res[2], res[3]);
            *(float4*)(out + (size_t)n * CC + loff + 4) = make_float4(res[4], res[5], res[6], res[7]);
        }
        if (doSplit) {
            __half hh[8], ll[8];
#pragma unroll
            for (int q = 0; q < 8; q++) {
                hh[q] = __float2half_rn(res[q]);
                ll[q] = __float2half_rn(res[q] - __half2float(hh[q]));
            }
            *(uint4*)(hi + (size_t)n * CC + loff) = *(uint4*)hh;
            *(uint4*)(lo + (size_t)n * CC + loff) = *(uint4*)ll;
        }
    }
}

// ---------------- launch ----------------
extern "C" void kernel_launch(void* const* d_in, const int* in_sizes, int n_in,
                              void* d_out, int out_size) {
    const float* x    = (const float*)d_in[0];
    const void*  ei   = d_in[1];
    const float* ea   = (const float*)d_in[2];
    const float* Wp1  = (const float*)d_in[3];
    const float* bp1  = (const float*)d_in[4];
    const float* Wp2  = (const float*)d_in[5];
    const float* bp2  = (const float*)d_in[6];
    const float* W[3]  = {(const float*)d_in[7],  (const float*)d_in[10], (const float*)d_in[13]};
    const float* Wr[3] = {(const float*)d_in[8],  (const float*)d_in[11], (const float*)d_in[14]};
    const float* b[3]  = {(const float*)d_in[9],  (const float*)d_in[12], (const float*)d_in[15]};
    float* out_final = (float*)d_out;

    __half* xwh_p;   cudaGetSymbolAddress((void**)&xwh_p, g_XWh);
    __half* xhi_p;   cudaGetSymbolAddress((void**)&xhi_p, g_xhi);
    __half* xlo_p;   cudaGetSymbolAddress((void**)&xlo_p, g_xlo);
    __half* bt_p;    cudaGetSymbolAddress((void**)&bt_p, g_bt);

    cudaFuncSetAttribute(xw_hmma_kernel, cudaFuncAttributeMaxDynamicSharedMemorySize, SMEM_TOT);

    // 1) CSR build: detect width, count, scan, fused MLP+scatter
    detect_idx_kernel<<<1, 32>>>((const unsigned int*)ei);
    zero_cnt_kernel<<<(NN + 255) / 256, 256>>>();
    count_kernel<<<(NE + 255) / 256, 256>>>(ei);
    blocksum_kernel<<<SCAN_BLKS, 256>>>();
    scanpart_kernel<<<1, 128>>>();
    rowptr_kernel<<<SCAN_BLKS, 256>>>();
    edge_csr_kernel<<<(NE + 255) / 256, 256>>>(ei, ea, Wp1, bp1, Wp2, bp2);

    // 2) weights: shared-tile transpose to fp16, root appended as block 27
    for (int l = 0; l < 3; l++) {
        conv_w_kernel<<<dim3(KK, 4), 256>>>(W[l], bt_p + (size_t)l * NB2 * CC, 0);
        conv_w_kernel<<<dim3(1, 4), 256>>>(Wr[l], bt_p + (size_t)l * NB2 * CC, 27);
    }

    // 3) layer-0 activation split
    convert_act_kernel<<<(NN * CC + 255) / 256, 256>>>(x, xhi_p, xlo_p);

    // 4) three layers
    dim3 gridXW(NB2 / 128, (NN + 127) / 128);   // 28 x 157
    int aggBlocks = (NN + 7) / 8;

    for (int l = 0; l < 3; l++) {
        xw_hmma_kernel<<<gridXW, 256, SMEM_TOT>>>(
            xhi_p, xlo_p, bt_p + (size_t)l * NB2 * CC, xwh_p);

        agg_csr_kernel<<<aggBlocks, 256>>>(
            xwh_p, b[l], (l == 2) ? out_final : nullptr, xhi_p, xlo_p,
            /*doRelu=*/(l < 2) ? 1 : 0,
            /*doOut=*/(l == 2) ? 1 : 0,
            /*doSplit=*/(l < 2) ? 1 : 0);
    }
}

// round 17
// speedup vs baseline: 1.4382x; 1.0296x over previous
#include <cuda_runtime.h>
#include <cuda_fp16.h>
#include <math.h>
#include <stdint.h>

// Problem constants
#define NN   20000          // nodes
#define NE   320000         // edges
#define CC   128            // channels
#define KK   27             // kernel matrices
#define NB2  (28 * CC)      // 3584 = 27 kernel blocks + 1 root block
#define EDGE_DIM 16
#define MLP_HID  6
#define SCAN_BLKS 79        // 79*256 >= NN

// ---------------- static device scratch ----------------
__device__ int   g_idx64;
// CSR by dst
__device__ int   g_cnt[NN];
__device__ int   g_rowptr[NN + 1];
__device__ int   g_woff[NN];
__device__ int   g_bsum[SCAN_BLKS];
__device__ int   g_bpre[SCAN_BLKS];
__device__ int   g_epack[NE];            // src | (kbase<<16), CSR order
__device__ float g_bwc[NE * 8];          // bw, CSR order
// GEMM buffers
__device__ __half g_XWh[(size_t)NN * NB2];            // 143 MB fp16
__device__ __half g_xhi[NN * CC];                     // activation hi (fp16)
__device__ __half g_xlo[NN * CC];                     // activation lo residual (fp16)
__device__ __half g_bt[3][(size_t)NB2 * CC];          // W^T fp16: [row=k*128+o][col=cin]

// ---------------- index width detection ----------------
__global__ void detect_idx_kernel(const unsigned int* __restrict__ ei) {
    if (blockIdx.x == 0 && threadIdx.x == 0) {
        int is64 = 1;
        for (int i = 0; i < 4096; i++) {
            if (ei[2 * i + 1] != 0u) { is64 = 0; break; }
        }
        g_idx64 = is64;
    }
}

__global__ void zero_cnt_kernel() {
    int i = blockIdx.x * blockDim.x + threadIdx.x;
    if (i < NN) g_cnt[i] = 0;
}

// ---------------- pass 1: count edges per dst ----------------
__global__ void count_kernel(const void* __restrict__ ei_raw) {
    int e = blockIdx.x * blockDim.x + threadIdx.x;
    if (e >= NE) return;
    int d;
    if (g_idx64) d = (int)((const long long*)ei_raw)[NE + e];
    else         d = ((const int*)ei_raw)[NE + e];
    atomicAdd(&g_cnt[d], 1);
}

// ---------------- 3-phase scan ----------------
__global__ void blocksum_kernel() {
    __shared__ int sh[256];
    int idx = blockIdx.x * 256 + threadIdx.x;
    int c = (idx < NN) ? g_cnt[idx] : 0;
    sh[threadIdx.x] = c;
    __syncthreads();
    for (int s = 128; s > 0; s >>= 1) {
        if (threadIdx.x < s) sh[threadIdx.x] += sh[threadIdx.x + s];
        __syncthreads();
    }
    if (threadIdx.x == 0) g_bsum[blockIdx.x] = sh[0];
}

__global__ void scanpart_kernel() {
    __shared__ int sh[128];
    int t = threadIdx.x;
    int v = (t < SCAN_BLKS) ? g_bsum[t] : 0;
    sh[t] = v;
    __syncthreads();
    for (int d = 1; d < 128; d <<= 1) {
        int u = (t >= d) ? sh[t - d] : 0;
        __syncthreads();
        sh[t] += u;
        __syncthreads();
    }
    if (t < SCAN_BLKS) g_bpre[t] = sh[t] - v;
    if (t == 0) g_rowptr[NN] = NE;
}

__global__ void rowptr_kernel() {
    __shared__ int sh[256];
    int idx = blockIdx.x * 256 + threadIdx.x;
    int t = threadIdx.x;
    int c = (idx < NN) ? g_cnt[idx] : 0;
    sh[t] = c;
    __syncthreads();
    for (int d = 1; d < 256; d <<= 1) {
        int u = (t >= d) ? sh[t - d] : 0;
        __syncthreads();
        sh[t] += u;
        __syncthreads();
    }
    if (idx < NN) {
        int excl = g_bpre[blockIdx.x] + sh[t] - c;
        g_rowptr[idx] = excl;
        g_woff[idx] = excl;
    }
}

// ---------------- pass 2: fused MLP + spline basis + direct CSR write ----------------
__global__ void edge_csr_kernel(const void* __restrict__ ei_raw,
                                const float* __restrict__ ea,
                                const float* __restrict__ Wp1,
                                const float* __restrict__ bp1,
                                const float* __restrict__ Wp2,
                                const float* __restrict__ bp2) {
    int e = blockIdx.x * blockDim.x + threadIdx.x;
    if (e >= NE) return;

    int s, d;
    if (g_idx64) {
        const long long* p = (const long long*)ei_raw;
        s = (int)p[e];
        d = (int)p[NE + e];
    } else {
        const int* p = (const int*)ei_raw;
        s = p[e];
        d = p[NE + e];
    }

    float a[EDGE_DIM];
#pragma unroll
    for (int i = 0; i < EDGE_DIM; i++) a[i] = ea[(size_t)e * EDGE_DIM + i];

    float h[MLP_HID];
#pragma unroll
    for (int j = 0; j < MLP_HID; j++) {
        float z = bp1[j];
#pragma unroll
        for (int i = 0; i < EDGE_DIM; i++) z += a[i] * Wp1[i * MLP_HID + j];
        h[j] = fmaxf(z, 0.0f);
    }

    float fr[3];
    int lo[3];
#pragma unroll
    for (int dd = 0; dd < 3; dd++) {
        float z = bp2[dd];
#pragma unroll
        for (int j = 0; j < MLP_HID; j++) z += h[j] * Wp2[j * 3 + dd];
        float u = 1.0f / (1.0f + expf(-z));
        float v = u * 2.0f;
        float l = fminf(fmaxf(floorf(v), 0.0f), 1.0f);
        lo[dd] = (int)l;
        fr[dd] = v - l;
    }
    int kb = lo[0] + 3 * lo[1] + 9 * lo[2];

    int pos = atomicAdd(&g_woff[d], 1);
    g_epack[pos] = s | (kb << 16);
#pragma unroll
    for (int sb = 0; sb < 8; sb++) {
        float w = ((sb & 1) ? fr[0] : 1.0f - fr[0])
                * ((sb & 2) ? fr[1] : 1.0f - fr[1])
                * ((sb & 4) ? fr[2] : 1.0f - fr[2]);
        g_bwc[(size_t)pos * 8 + sb] = w;
    }
}

// -------- W [nk,Cin,H] fp32 -> Bt rows [(kbase+k)*H+o], cols [Cin] fp16 --------
__global__ void conv_w_kernel(const float* __restrict__ W, __half* __restrict__ bt, int kbase) {
    __shared__ float tile[32][129];
    const int k = blockIdx.x;
    const int chunk = blockIdx.y;
#pragma unroll
    for (int it = 0; it < 16; it++) {
        int idx = it * 256 + threadIdx.x;
        int r = idx >> 7, o = idx & 127;
        tile[r][o] = W[((size_t)k * 128 + chunk * 32 + r) * 128 + o];
    }
    __syncthreads();
#pragma unroll
    for (int it = 0; it < 16; it++) {
        int idx = it * 256 + threadIdx.x;
        int o = idx >> 5, i = idx & 31;
        bt[(size_t)((kbase + k) * 128 + o) * 128 + chunk * 32 + i] =
            __float2half_rn(tile[i][o]);
    }
}

// -------- activation fp32 -> fp16 hi/lo split (layer 0 only) --------
__global__ void convert_act_kernel(const float* __restrict__ a,
                                   __half* __restrict__ hi,
                                   __half* __restrict__ lo) {
    int i = blockIdx.x * blockDim.x + threadIdx.x;
    if (i >= NN * CC) return;
    float v = a[i];
    __half h = __float2half_rn(v);
    hi[i] = h;
    lo[i] = __float2half_rn(v - __half2float(h));
}

// ================= HMMA (mma.sync fp16) merged 2-pass GEMM: XWh = act @ Bt^T =================
// D = Ahi*B + Alo*B, fp32 accum; single ks loop, B fragments loaded ONCE per ks.
#define SM_AHI 0
#define SM_ALO 32768
#define SM_B   65536
#define SMEM_TOT 98304

__device__ __forceinline__ uint32_t smem_u32(const void* p) {
    uint32_t a;
    asm("{ .reg .u64 t; cvta.to.shared.u64 t, %1; cvt.u32.u64 %0, t; }" : "=r"(a) : "l"(p));
    return a;
}
__device__ __forceinline__ uint32_t sw_off(int row, int kc) {
    return (uint32_t)(row * 256 + ((kc ^ (row & 7)) << 4));
}
__device__ __forceinline__ void load_tile(char* smem, int off,
                                          const __half* __restrict__ src,
                                          int row_base, int row_max, int tid) {
#pragma unroll
    for (int it = 0; it < 8; it++) {
        int idx = it * 256 + tid;
        int row = idx >> 4, kc = idx & 15;
        int grow = row_base + row;
        uint4 v = make_uint4(0u, 0u, 0u, 0u);
        if (grow < row_max)
            v = *(const uint4*)(src + (size_t)grow * CC + kc * 8);
        *(uint4*)(smem + off + sw_off(row, kc)) = v;
    }
}
__device__ __forceinline__ void ldmatrix_x4(uint32_t* r, uint32_t addr) {
    asm volatile("ldmatrix.sync.aligned.m8n8.x4.shared.b16 {%0,%1,%2,%3}, [%4];"
                 : "=r"(r[0]), "=r"(r[1]), "=r"(r[2]), "=r"(r[3]) : "r"(addr));
}
__device__ __forceinline__ void mma16816(float* c, const uint32_t* a, const uint32_t* b) {
    asm volatile(
        "mma.sync.aligned.m16n8k16.row.col.f32.f16.f16.f32 "
        "{%0,%1,%2,%3}, {%4,%5,%6,%7}, {%8,%9}, {%0,%1,%2,%3};"
        : "+f"(c[0]), "+f"(c[1]), "+f"(c[2]), "+f"(c[3])
        : "r"(a[0]), "r"(a[1]), "r"(a[2]), "r"(a[3]), "r"(b[0]), "r"(b[1]));
}

__global__ void __launch_bounds__(256, 2)
xw_hmma_kernel(const __half* __restrict__ xhi,
               const __half* __restrict__ xlo,
               const __half* __restrict__ bt,
               __half* __restrict__ XWh) {
    extern __shared__ __align__(1024) char smem[];
    const int tid  = threadIdx.x;
    const int wid  = tid >> 5;
    const int lane = tid & 31;
    const int bn = blockIdx.x * 128;
    const int bm = blockIdx.y * 128;

    load_tile(smem, SM_AHI, xhi, bm, NN, tid);
    load_tile(smem, SM_B,   bt,  bn, NB2, tid);
    load_tile(smem, SM_ALO, xlo, bm, NN, tid);
    __syncthreads();

    const uint32_t sbase = smem_u32(smem);
    const int m_base = (wid & 1) * 64;
    const int n_base = (wid >> 1) * 32;

    float acc[4][4][4];
#pragma unroll
    for (int mt = 0; mt < 4; mt++)
#pragma unroll
        for (int nt = 0; nt < 4; nt++)
#pragma unroll
            for (int q = 0; q < 4; q++) acc[mt][nt][q] = 0.0f;

    const int a_row_in = (lane & 15);
    const int a_kadd   = (lane >> 4);
    const int b_row_in = ((lane >> 4) << 3) + (lane & 7);
    const int b_kadd   = ((lane >> 3) & 1);

    const uint32_t ahib = sbase + SM_AHI;
    const uint32_t alob = sbase + SM_ALO;
    const uint32_t bb   = sbase + SM_B;

#pragma unroll
    for (int ks = 0; ks < 8; ks++) {
        const int kc = ks * 2;
        // B fragments: loaded once, used by both A passes
        uint32_t bfrag[4][2];
#pragma unroll
        for (int g = 0; g < 2; g++) {
            uint32_t r[4];
            int nrow = n_base + g * 16 + b_row_in;
            ldmatrix_x4(r, bb + sw_off(nrow, kc + b_kadd));
            bfrag[2 * g][0]     = r[0];
            bfrag[2 * g][1]     = r[1];
            bfrag[2 * g + 1][0] = r[2];
            bfrag[2 * g + 1][1] = r[3];
        }
        // pass 1: Ahi
        {
            uint32_t afrag[4][4];
#pragma unroll
            for (int mt = 0; mt < 4; mt++) {
                int row = m_base + mt * 16 + a_row_in;
                ldmatrix_x4(afrag[mt], ahib + sw_off(row, kc + a_kadd));
            }
#pragma unroll
            for (int mt = 0; mt < 4; mt++)
#pragma unroll
                for (int nt = 0; nt < 4; nt++)
                    mma16816(acc[mt][nt], afrag[mt], bfrag[nt]);
        }
        // pass 2: Alo
        {
            uint32_t afrag[4][4];
#pragma unroll
            for (int mt = 0; mt < 4; mt++) {
                int row = m_base + mt * 16 + a_row_in;
                ldmatrix_x4(afrag[mt], alob + sw_off(row, kc + a_kadd));
            }
#pragma unroll
            for (int mt = 0; mt < 4; mt++)
#pragma unroll
                for (int nt = 0; nt < 4; nt++)
                    mma16816(acc[mt][nt], afrag[mt], bfrag[nt]);
        }
    }

    // epilogue: fp16 store
    const int qrow = lane >> 2;
    const int qcol = (lane & 3) * 2;
#pragma unroll
    for (int mt = 0; mt < 4; mt++) {
        int r0 = bm + m_base + mt * 16 + qrow;
        int r1 = r0 + 8;
#pragma unroll
        for (int nt = 0; nt < 4; nt++) {
            int col = bn + n_base + nt * 8 + qcol;
            if (r0 < NN) {
                __half2 h = __floats2half2_rn(acc[mt][nt][0], acc[mt][nt][1]);
                *(uint32_t*)(XWh + (size_t)r0 * NB2 + col) = *(uint32_t*)&h;
            }
            if (r1 < NN) {
                __half2 h = __floats2half2_rn(acc[mt][nt][2], acc[mt][nt][3]);
                *(uint32_t*)(XWh + (size_t)r1 * NB2 + col) = *(uint32_t*)&h;
            }
        }
    }
}

// ======== fused aggregation: tap-pair uint4 gathers, 8-edge pipeline ========
__global__ void __launch_bounds__(256)
agg_csr_kernel(const __half* __restrict__ XWh,
               const float* __restrict__ bias,
               float* __restrict__ out,
               __half* __restrict__ hi,
               __half* __restrict__ lo,
               int doRelu, int doOut, int doSplit) {
    const int n = blockIdx.x * 8 + (threadIdx.x >> 5);
    const int lane = threadIdx.x & 31;
    if (n >= NN) return;
    const int POFF[4] = {0, 384, 1152, 1536};  // {0,3,9,12}*128 halfs
    const int phase = lane >> 4;               // 0: even tap of pair, 1: odd tap
    const int loff  = lane * 8;                // half offset within 512B pair segment

    float acc[8];
#pragma unroll
    for (int q = 0; q < 8; q++) acc[q] = 0.0f;

    const int beg = g_rowptr[n];
    const int end = g_rowptr[n + 1];
    int i = beg;
    // 8-edge pipelined main loop: 32 independent uint4 gathers in flight
    for (; i + 8 <= end; i += 8) {
        int pk[8];
#pragma unroll
        for (int j = 0; j < 8; j++) pk[j] = g_epack[i + j];
        float wv0 = g_bwc[(size_t)i * 8 + lane];
        float wv1 = g_bwc[(size_t)(i + 4) * 8 + lane];
        const __half* bs[8];
#pragma unroll
        for (int j = 0; j < 8; j++)
            bs[j] = XWh + (size_t)(pk[j] & 0xffff) * NB2 + (size_t)(pk[j] >> 16) * CC + loff;
#pragma unroll
        for (int p = 0; p < 4; p++) {
            int ts = 2 * p + phase;
            float w[8];
#pragma unroll
            for (int j = 0; j < 4; j++) {
                w[j]     = __shfl_sync(0xffffffffu, wv0, 8 * j + ts);
                w[4 + j] = __shfl_sync(0xffffffffu, wv1, 8 * j + ts);
            }
            uint4 v[8];
#pragma unroll
            for (int j = 0; j < 8; j++) v[j] = *(const uint4*)(bs[j] + POFF[p]);
#pragma unroll
            for (int j = 0; j < 8; j++) {
                const uint32_t* u = &v[j].x;
#pragma unroll
                for (int q = 0; q < 4; q++) {
                    float2 f = __half22float2(*(const __half2*)&u[q]);
                    acc[2 * q]     += w[j] * f.x;
                    acc[2 * q + 1] += w[j] * f.y;
                }
            }
        }
    }
    // 4-edge step
    for (; i + 4 <= end; i += 4) {
        int pk[4];
#pragma unroll
        for (int j = 0; j < 4; j++) pk[j] = g_epack[i + j];
        float wv0 = g_bwc[(size_t)i * 8 + lane];
        const __half* bs[4];
#pragma unroll
        for (int j = 0; j < 4; j++)
            bs[j] = XWh + (size_t)(pk[j] & 0xffff) * NB2 + (size_t)(pk[j] >> 16) * CC + loff;
#pragma unroll
        for (int p = 0; p < 4; p++) {
            int ts = 2 * p + phase;
            float w[4];
#pragma unroll
            for (int j = 0; j < 4; j++) w[j] = __shfl_sync(0xffffffffu, wv0, 8 * j + ts);
            uint4 v[4];
#pragma unroll
            for (int j = 0; j < 4; j++) v[j] = *(const uint4*)(bs[j] + POFF[p]);
#pragma unroll
            for (int j = 0; j < 4; j++) {
                const uint32_t* u = &v[j].x;
#pragma unroll
                for (int q = 0; q < 4; q++) {
                    float2 f = __half22float2(*(const __half2*)&u[q]);
                    acc[2 * q]     += w[j] * f.x;
                    acc[2 * q + 1] += w[j] * f.y;
                }
            }
        }
    }
    // single-edge tail
    for (; i < end; i++) {
        int p0 = g_epack[i];
        float wv = (lane < 8) ? g_bwc[(size_t)i * 8 + lane] : 0.0f;
        const __half* b0 = XWh + (size_t)(p0 & 0xffff) * NB2 + (size_t)(p0 >> 16) * CC + loff;
#pragma unroll
        for (int p = 0; p < 4; p++) {
            float w0 = __shfl_sync(0xffffffffu, wv, 2 * p + phase);
            uint4 v0 = *(const uint4*)(b0 + POFF[p]);
            const uint32_t* u0 = &v0.x;
#pragma unroll
            for (int q = 0; q < 4; q++) {
                float2 f0 = __half22float2(*(const __half2*)&u0[q]);
                acc[2 * q]     += w0 * f0.x;
                acc[2 * q + 1] += w0 * f0.y;
            }
        }
    }

    // merge phases: lane L (<16) gets odd-tap partial from lane L+16
#pragma unroll
    for (int q = 0; q < 8; q++)
        acc[q] += __shfl_down_sync(0xffffffffu, acc[q], 16);

    if (lane < 16) {
        uint4 rv = *(const uint4*)(XWh + (size_t)n * NB2 + 27 * CC + loff);
        const uint32_t* ru = &rv.x;
        float4 bb0 = *(const float4*)(bias + loff);
        float4 bb1 = *(const float4*)(bias + loff + 4);
        float res[8];
#pragma unroll
        for (int j = 0; j < 4; j++) {
            float2 f = __half22float2(*(const __half2*)&ru[j]);
            res[2 * j]     = acc[2 * j]     + f.x;
            res[2 * j + 1] = acc[2 * j + 1] + f.y;
        }
        res[0] += bb0.x; res[1] += bb0.y; res[2] += bb0.z; res[3] += bb0.w;
        res[4] += bb1.x; res[5] += bb1.y; res[6] += bb1.z; res[7] += bb1.w;

        if (doRelu) {
#pragma unroll
            for (int q = 0; q < 8; q++) res[q] = fmaxf(res[q], 0.0f);
        }
        if (doOut) {
            *(float4*)(out + (size_t)n * CC + loff)     = make_float4(res[0], res[1], res[2], res[3]);
            *(float4*)(out + (size_t)n * CC + loff + 4) = make_float4(res[4], res[5], res[6], res[7]);
        }
        if (doSplit) {
            __half hh[8], ll[8];
#pragma unroll
            for (int q = 0; q < 8; q++) {
                hh[q] = __float2half_rn(res[q]);
                ll[q] = __float2half_rn(res[q] - __half2float(hh[q]));
            }
            *(uint4*)(hi + (size_t)n * CC + loff) = *(uint4*)hh;
            *(uint4*)(lo + (size_t)n * CC + loff) = *(uint4*)ll;
        }
    }
}

// ---------------- launch ----------------
extern "C" void kernel_launch(void* const* d_in, const int* in_sizes, int n_in,
                              void* d_out, int out_size) {
    const float* x    = (const float*)d_in[0];
    const void*  ei   = d_in[1];
    const float* ea   = (const float*)d_in[2];
    const float* Wp1  = (const float*)d_in[3];
    const float* bp1  = (const float*)d_in[4];
    const float* Wp2  = (const float*)d_in[5];
    const float* bp2  = (const float*)d_in[6];
    const float* W[3]  = {(const float*)d_in[7],  (const float*)d_in[10], (const float*)d_in[13]};
    const float* Wr[3] = {(const float*)d_in[8],  (const float*)d_in[11], (const float*)d_in[14]};
    const float* b[3]  = {(const float*)d_in[9],  (const float*)d_in[12], (const float*)d_in[15]};
    float* out_final = (float*)d_out;

    __half* xwh_p;   cudaGetSymbolAddress((void**)&xwh_p, g_XWh);
    __half* xhi_p;   cudaGetSymbolAddress((void**)&xhi_p, g_xhi);
    __half* xlo_p;   cudaGetSymbolAddress((void**)&xlo_p, g_xlo);
    __half* bt_p;    cudaGetSymbolAddress((void**)&bt_p, g_bt);

    cudaFuncSetAttribute(xw_hmma_kernel, cudaFuncAttributeMaxDynamicSharedMemorySize, SMEM_TOT);

    // 1) CSR build: detect width, count, scan, fused MLP+scatter
    detect_idx_kernel<<<1, 32>>>((const unsigned int*)ei);
    zero_cnt_kernel<<<(NN + 255) / 256, 256>>>();
    count_kernel<<<(NE + 255) / 256, 256>>>(ei);
    blocksum_kernel<<<SCAN_BLKS, 256>>>();
    scanpart_kernel<<<1, 128>>>();
    rowptr_kernel<<<SCAN_BLKS, 256>>>();
    edge_csr_kernel<<<(NE + 255) / 256, 256>>>(ei, ea, Wp1, bp1, Wp2, bp2);

    // 2) weights: shared-tile transpose to fp16, root appended as block 27
    for (int l = 0; l < 3; l++) {
        conv_w_kernel<<<dim3(KK, 4), 256>>>(W[l], bt_p + (size_t)l * NB2 * CC, 0);
        conv_w_kernel<<<dim3(1, 4), 256>>>(Wr[l], bt_p + (size_t)l * NB2 * CC, 27);
    }

    // 3) layer-0 activation split
    convert_act_kernel<<<(NN * CC + 255) / 256, 256>>>(x, xhi_p, xlo_p);

    // 4) three layers
    dim3 gridXW(NB2 / 128, (NN + 127) / 128);   // 28 x 157
    int aggBlocks = (NN + 7) / 8;

    for (int l = 0; l < 3; l++) {
        xw_hmma_kernel<<<gridXW, 256, SMEM_TOT>>>(
            xhi_p, xlo_p, bt_p + (size_t)l * NB2 * CC, xwh_p);

        agg_csr_kernel<<<aggBlocks, 256>>>(
            xwh_p, b[l], (l == 2) ? out_final : nullptr, xhi_p, xlo_p,
            /*doRelu=*/(l < 2) ? 1 : 0,
            /*doOut=*/(l == 2) ? 1 : 0,
            /*doSplit=*/(l < 2) ? 1 : 0);
    }
}